// round 9
// baseline (speedup 1.0000x reference)
#include <cuda_runtime.h>
#include <stdint.h>
#include <math.h>

#define BDIM 4
#define SDIM 4096
#define DDIM 1024

// Scratch (device globals — allocation-free per harness rules)
__device__ float g_qkv[(size_t)BDIM * SDIM * 3 * DDIM];  // [B*S, 3D]
__device__ float g_wt [(size_t)3 * DDIM * DDIM];         // W^T  [3D, D]
__device__ float g_vt [(size_t)BDIM * DDIM * SDIM];      // V^T  [B][D][S]
__device__ float g_sc [(size_t)BDIM * SDIM * SDIM];      // scores / attn [B][S][S]

// ---------------------------------------------------------------------------
// tf32 helpers (arch-portable PTX only — NO tcgen05; harness targets sm_103 base)
// ---------------------------------------------------------------------------
__device__ __forceinline__ uint32_t f2tf32(float f) {
    uint32_t r; asm("cvt.rna.tf32.f32 %0, %1;" : "=r"(r) : "f"(f)); return r;
}

__device__ __forceinline__ void mma16n8k8(float c[4],
                                          uint32_t a0, uint32_t a1, uint32_t a2, uint32_t a3,
                                          uint32_t b0, uint32_t b1) {
    asm volatile(
        "mma.sync.aligned.m16n8k8.row.col.f32.tf32.tf32.f32 "
        "{%0,%1,%2,%3}, {%4,%5,%6,%7}, {%8,%9}, {%0,%1,%2,%3};"
        : "+f"(c[0]), "+f"(c[1]), "+f"(c[2]), "+f"(c[3])
        : "r"(a0), "r"(a1), "r"(a2), "r"(a3), "r"(b0), "r"(b1));
}

// ---------------------------------------------------------------------------
// TN tf32 GEMM via mma.sync: C[M,N] = A[M,K] @ B[N,K]^T (+ bias[N]). Batched z.
// CTA 128x128x16, 128 threads (4 warps = 2M x 2N, warp tile 64x64).
// 2 CTAs/SM. gmem->reg prefetch, cvt.rna at staging, double-buffered SMEM.
// ROWP=20: fragment LDS banks (20g+tq) mod 32 all-distinct -> conflict-free;
// staging STS.128 8-lane phases cover all 32 banks -> conflict-free.
// ---------------------------------------------------------------------------
#define TM 128
#define TN 128
#define TK 16
#define ROWP 20                               // padded row length (floats)
#define TILE_U (128 * ROWP)                   // one operand tile in u32 (2560)
#define SMEM_BYTES (4 * TILE_U * 4)           // A0 B0 A1 B1 = 40960 B

extern __shared__ uint32_t smu[];

__global__ __launch_bounds__(128, 2)
void gemm_tf32mma(const float* __restrict__ A, int lda, long long sA,
                  const float* __restrict__ B, int ldb, long long sB,
                  float* __restrict__ C, int ldc, long long sC,
                  int K, const float* __restrict__ bias)
{
    const int tid = threadIdx.x;
    const int wid = tid >> 5, lid = tid & 31;
    const int g = lid >> 2, tq = lid & 3;      // mma group / quad
    const int wm = wid & 1, wn = wid >> 1;     // warp position: 2(M) x 2(N)
    const int bx = blockIdx.x, by = blockIdx.y, bz = blockIdx.z;

    A += (long long)bz * sA + (long long)(by * TM) * lda;
    B += (long long)bz * sB + (long long)(bx * TN) * ldb;
    C += (long long)bz * sC + (long long)(by * TM) * ldc + bx * TN;

    uint32_t* As0 = smu;                 // buffers: [A0][B0][A1][B1]
    uint32_t* Bs0 = smu + TILE_U;

    // Staging map: 1 thread per row, 16 floats (4 x float4)
    const float* Ap = A + (long long)tid * lda;
    const float* Bp = B + (long long)tid * ldb;
    const int soff = tid * ROWP;

    float acc[4][8][4];
    #pragma unroll
    for (int i = 0; i < 4; i++)
        #pragma unroll
        for (int j = 0; j < 8; j++)
            #pragma unroll
            for (int r = 0; r < 4; r++) acc[i][j][r] = 0.f;

    // ---- stage tile 0 into buffer 0 ----
    #pragma unroll
    for (int i = 0; i < 4; i++) {
        float4 va = *(const float4*)(Ap + i * 4);
        float4 vb = *(const float4*)(Bp + i * 4);
        As0[soff + i * 4 + 0] = f2tf32(va.x); As0[soff + i * 4 + 1] = f2tf32(va.y);
        As0[soff + i * 4 + 2] = f2tf32(va.z); As0[soff + i * 4 + 3] = f2tf32(va.w);
        Bs0[soff + i * 4 + 0] = f2tf32(vb.x); Bs0[soff + i * 4 + 1] = f2tf32(vb.y);
        Bs0[soff + i * 4 + 2] = f2tf32(vb.z); Bs0[soff + i * 4 + 3] = f2tf32(vb.w);
    }
    __syncthreads();

    const int NK = K / TK;
    const int aBase = (wm * 64 + g) * ROWP;    // + mb*16*ROWP (+8*ROWP)
    const int bBase = (wn * 64 + g) * ROWP;    // + nb*8*ROWP

    for (int t = 0; t < NK; ++t) {
        const int cur = t & 1;
        const uint32_t* Ac = As0 + cur * 2 * TILE_U;
        const uint32_t* Bc = Bs0 + cur * 2 * TILE_U;

        // prefetch next k-tile from gmem (overlaps with MMAs below)
        const bool more = (t + 1 < NK);
        float4 pa[4], pb[4];
        if (more) {
            const float* An = Ap + (t + 1) * TK;
            const float* Bn = Bp + (t + 1) * TK;
            #pragma unroll
            for (int i = 0; i < 4; i++) {
                pa[i] = *(const float4*)(An + i * 4);
                pb[i] = *(const float4*)(Bn + i * 4);
            }
        }

        // ---- compute: 2 k-steps of k=8, warp tile 64x64 (32 MMAs/step) ----
        #pragma unroll
        for (int ks = 0; ks < 2; ++ks) {
            const int c0 = ks * 8 + tq;
            uint32_t af[4][4], bf[8][2];
            #pragma unroll
            for (int mb = 0; mb < 4; mb++) {
                const int r = aBase + mb * 16 * ROWP;
                af[mb][0] = Ac[r + c0];
                af[mb][1] = Ac[r + 8 * ROWP + c0];
                af[mb][2] = Ac[r + c0 + 4];
                af[mb][3] = Ac[r + 8 * ROWP + c0 + 4];
            }
            #pragma unroll
            for (int nb = 0; nb < 8; nb++) {
                const int r = bBase + nb * 8 * ROWP;
                bf[nb][0] = Bc[r + c0];
                bf[nb][1] = Bc[r + c0 + 4];
            }
            #pragma unroll
            for (int mb = 0; mb < 4; mb++)
                #pragma unroll
                for (int nb = 0; nb < 8; nb++)
                    mma16n8k8(acc[mb][nb], af[mb][0], af[mb][1], af[mb][2], af[mb][3],
                              bf[nb][0], bf[nb][1]);
        }

        // ---- stage next tile into the other buffer ----
        if (more) {
            uint32_t* An = As0 + (cur ^ 1) * 2 * TILE_U;
            uint32_t* Bn = Bs0 + (cur ^ 1) * 2 * TILE_U;
            #pragma unroll
            for (int i = 0; i < 4; i++) {
                An[soff + i * 4 + 0] = f2tf32(pa[i].x); An[soff + i * 4 + 1] = f2tf32(pa[i].y);
                An[soff + i * 4 + 2] = f2tf32(pa[i].z); An[soff + i * 4 + 3] = f2tf32(pa[i].w);
                Bn[soff + i * 4 + 0] = f2tf32(pb[i].x); Bn[soff + i * 4 + 1] = f2tf32(pb[i].y);
                Bn[soff + i * 4 + 2] = f2tf32(pb[i].z); Bn[soff + i * 4 + 3] = f2tf32(pb[i].w);
            }
        }
        __syncthreads();
    }

    // ---- epilogue ----
    float badd[8][2];
    #pragma unroll
    for (int nb = 0; nb < 8; nb++) {
        const int col = wn * 64 + nb * 8 + tq * 2;
        badd[nb][0] = bias ? __ldg(bias + bx * TN + col)     : 0.f;
        badd[nb][1] = bias ? __ldg(bias + bx * TN + col + 1) : 0.f;
    }
    #pragma unroll
    for (int mb = 0; mb < 4; mb++) {
        const int row = wm * 64 + mb * 16 + g;
        #pragma unroll
        for (int nb = 0; nb < 8; nb++) {
            const int col = wn * 64 + nb * 8 + tq * 2;
            float2 v0 = make_float2(acc[mb][nb][0] + badd[nb][0],
                                    acc[mb][nb][1] + badd[nb][1]);
            float2 v1 = make_float2(acc[mb][nb][2] + badd[nb][0],
                                    acc[mb][nb][3] + badd[nb][1]);
            *(float2*)(C + (long long)row * ldc + col)       = v0;
            *(float2*)(C + (long long)(row + 8) * ldc + col) = v1;
        }
    }
}

// ---------------------------------------------------------------------------
// Generic 32x32 tiled transpose: out[c][r] = in[r][c], batched.
// ---------------------------------------------------------------------------
__global__ void transpose_f32(const float* __restrict__ in, long long sIn, int ldin,
                              float* __restrict__ out, long long sOut, int ldout)
{
    __shared__ float tile[32][33];
    const int b  = blockIdx.z;
    const int c0 = blockIdx.x << 5;
    const int r0 = blockIdx.y << 5;
    const int x = threadIdx.x, y = threadIdx.y;     // 32 x 8
    const float* ip = in + (long long)b * sIn;
    float* op = out + (long long)b * sOut;
    #pragma unroll
    for (int j = 0; j < 32; j += 8)
        tile[y + j][x] = ip[(long long)(r0 + y + j) * ldin + c0 + x];
    __syncthreads();
    #pragma unroll
    for (int j = 0; j < 32; j += 8)
        op[(long long)(c0 + y + j) * ldout + r0 + x] = tile[x][y + j];
}

// ---------------------------------------------------------------------------
// Row softmax over 4096 columns (scale folded in). Already at DRAM roofline.
// ---------------------------------------------------------------------------
__device__ __forceinline__ float warpMax(float v) {
    #pragma unroll
    for (int o = 16; o > 0; o >>= 1) v = fmaxf(v, __shfl_xor_sync(0xffffffffu, v, o));
    return v;
}
__device__ __forceinline__ float warpSum(float v) {
    #pragma unroll
    for (int o = 16; o > 0; o >>= 1) v += __shfl_xor_sync(0xffffffffu, v, o);
    return v;
}

__global__ __launch_bounds__(256, 4)
void softmax4096(float* __restrict__ s, float scale)
{
    float* p = s + (long long)blockIdx.x * 4096;
    const int t = threadIdx.x;
    const int lane = t & 31, wid = t >> 5;
    __shared__ float red[8];

    float4 v[4];
    #pragma unroll
    for (int i = 0; i < 4; i++) {
        v[i] = *(const float4*)(p + i * 1024 + t * 4);
        v[i].x *= scale; v[i].y *= scale; v[i].z *= scale; v[i].w *= scale;
    }
    float m = v[0].x;
    #pragma unroll
    for (int i = 0; i < 4; i++) {
        m = fmaxf(m, v[i].x); m = fmaxf(m, v[i].y);
        m = fmaxf(m, v[i].z); m = fmaxf(m, v[i].w);
    }
    m = warpMax(m);
    if (lane == 0) red[wid] = m;
    __syncthreads();
    m = red[0];
    #pragma unroll
    for (int j = 1; j < 8; j++) m = fmaxf(m, red[j]);

    float sum = 0.f;
    #pragma unroll
    for (int i = 0; i < 4; i++) {
        v[i].x = expf(v[i].x - m); v[i].y = expf(v[i].y - m);
        v[i].z = expf(v[i].z - m); v[i].w = expf(v[i].w - m);
        sum += v[i].x + v[i].y + v[i].z + v[i].w;
    }
    sum = warpSum(sum);
    __syncthreads();
    if (lane == 0) red[wid] = sum;
    __syncthreads();
    float tot = red[0];
    #pragma unroll
    for (int j = 1; j < 8; j++) tot += red[j];
    const float inv = 1.0f / tot;

    #pragma unroll
    for (int i = 0; i < 4; i++) {
        v[i].x *= inv; v[i].y *= inv; v[i].z *= inv; v[i].w *= inv;
        *(float4*)(p + i * 1024 + t * 4) = v[i];
    }
}

// ---------------------------------------------------------------------------
// Launch
// ---------------------------------------------------------------------------
extern "C" void kernel_launch(void* const* d_in, const int* in_sizes, int n_in,
                              void* d_out, int out_size)
{
    (void)in_sizes; (void)n_in; (void)out_size;
    const float* x = (const float*)d_in[0];   // [B,S,D]
    const float* W = (const float*)d_in[1];   // [D,3D]
    const float* b = (const float*)d_in[2];   // [3D]
    float* out = (float*)d_out;               // [B,S,D]

    float *qkv, *wt, *vt, *sc;
    cudaGetSymbolAddress((void**)&qkv, g_qkv);
    cudaGetSymbolAddress((void**)&wt,  g_wt);
    cudaGetSymbolAddress((void**)&vt,  g_vt);
    cudaGetSymbolAddress((void**)&sc,  g_sc);

    cudaFuncSetAttribute(gemm_tf32mma, cudaFuncAttributeMaxDynamicSharedMemorySize, SMEM_BYTES);

    // 0) Wt[e][d] = W[d][e]
    transpose_f32<<<dim3(3 * DDIM / 32, DDIM / 32, 1), dim3(32, 8)>>>(
        W, 0LL, 3 * DDIM, wt, 0LL, DDIM);

    // 1) qkv = x @ Wt^T + b   (M=16384, N=3072, K=1024)
    gemm_tf32mma<<<dim3(3 * DDIM / TN, BDIM * SDIM / TM, 1), 128, SMEM_BYTES>>>(
        x,   DDIM, 0LL,
        wt,  DDIM, 0LL,
        qkv, 3 * DDIM, 0LL,
        DDIM, b);

    // 2) Vt[b][d][s] = V[b][s][d]
    transpose_f32<<<dim3(DDIM / 32, SDIM / 32, BDIM), dim3(32, 8)>>>(
        qkv + 2 * DDIM, (long long)SDIM * 3 * DDIM, 3 * DDIM,
        vt,             (long long)DDIM * SDIM,     SDIM);

    // 3) scores = Q @ K^T   (per batch: M=4096, N=4096, K=1024)
    gemm_tf32mma<<<dim3(SDIM / TN, SDIM / TM, BDIM), 128, SMEM_BYTES>>>(
        qkv,        3 * DDIM, (long long)SDIM * 3 * DDIM,
        qkv + DDIM, 3 * DDIM, (long long)SDIM * 3 * DDIM,
        sc,         SDIM,     (long long)SDIM * SDIM,
        DDIM, (const float*)0);

    // 4) softmax rows (scale = D^-0.5 = 1/32)
    softmax4096<<<BDIM * SDIM, 256>>>(sc, 0.03125f);

    // 5) out = P @ Vt^T   (per batch: M=4096, N=1024, K=4096)
    gemm_tf32mma<<<dim3(DDIM / TN, SDIM / TM, BDIM), 128, SMEM_BYTES>>>(
        sc,  SDIM, (long long)SDIM * SDIM,
        vt,  SDIM, (long long)DDIM * SDIM,
        out, DDIM, (long long)SDIM * DDIM,
        SDIM, (const float*)0);
}

// round 10
// speedup vs baseline: 1.0954x; 1.0954x over previous
#include <cuda_runtime.h>
#include <stdint.h>
#include <math.h>

#define BDIM 4
#define SDIM 4096
#define DDIM 1024

// Scratch (device globals — allocation-free per harness rules)
__device__ float g_qkv[(size_t)BDIM * SDIM * 3 * DDIM];  // [B*S, 3D]
__device__ float g_wt [(size_t)3 * DDIM * DDIM];         // W^T  [3D, D]
__device__ float g_vt [(size_t)BDIM * DDIM * SDIM];      // V^T  [B][D][S]
__device__ float g_sc [(size_t)BDIM * SDIM * SDIM];      // scores / attn [B][S][S]

// ---------------------------------------------------------------------------
// Arch-portable PTX helpers (NO tcgen05 — harness targets sm_103 base)
// ---------------------------------------------------------------------------
__device__ __forceinline__ uint32_t f2tf32(float f) {
    uint32_t r; asm("cvt.rna.tf32.f32 %0, %1;" : "=r"(r) : "f"(f)); return r;
}
__device__ __forceinline__ uint32_t smem_u32(const void* p) {
    uint32_t a;
    asm("{ .reg .u64 t; cvta.to.shared.u64 t, %1; cvt.u32.u64 %0, t; }" : "=r"(a) : "l"(p));
    return a;
}
__device__ __forceinline__ void mma16n8k8(float c[4],
                                          uint32_t a0, uint32_t a1, uint32_t a2, uint32_t a3,
                                          uint32_t b0, uint32_t b1) {
    asm volatile(
        "mma.sync.aligned.m16n8k8.row.col.f32.tf32.tf32.f32 "
        "{%0,%1,%2,%3}, {%4,%5,%6,%7}, {%8,%9}, {%0,%1,%2,%3};"
        : "+f"(c[0]), "+f"(c[1]), "+f"(c[2]), "+f"(c[3])
        : "r"(a0), "r"(a1), "r"(a2), "r"(a3), "r"(b0), "r"(b1));
}
__device__ __forceinline__ void ldsm4(uint32_t& r0, uint32_t& r1, uint32_t& r2, uint32_t& r3,
                                      uint32_t addr) {
    asm volatile("ldmatrix.sync.aligned.m8n8.x4.shared.b16 {%0,%1,%2,%3}, [%4];"
                 : "=r"(r0), "=r"(r1), "=r"(r2), "=r"(r3) : "r"(addr));
}
__device__ __forceinline__ void sts128(uint32_t a, uint32_t x, uint32_t y, uint32_t z, uint32_t w) {
    asm volatile("st.shared.v4.b32 [%0], {%1,%2,%3,%4};" :: "r"(a), "r"(x), "r"(y), "r"(z), "r"(w));
}

// ---------------------------------------------------------------------------
// TN tf32 GEMM via mma.sync + ldmatrix: C[M,N] = A[M,K] @ B[N,K]^T (+ bias).
// CTA 128x128x16, 128 threads (4 warps = 2M x 2N, warp tile 64x64), 2 CTA/SM.
// Fragments via ldmatrix.x4 (one per m16k8 A frag; one per TWO n8k8 B frags).
// ROWP=20 floats: LDSM 8-row fetches and STS.128 phases hit all 32 banks.
// ---------------------------------------------------------------------------
#define TM 128
#define TN 128
#define TK 16
#define ROWP 20
#define TILE_U (128 * ROWP)                   // one operand tile in u32 (2560)
#define SMEM_BYTES (4 * TILE_U * 4)           // [A0][B0][A1][B1] = 40960 B
#define TILE_BYTES (TILE_U * 4)

extern __shared__ uint32_t smu[];

__global__ __launch_bounds__(128, 2)
void gemm_tf32mma(const float* __restrict__ A, int lda, long long sA,
                  const float* __restrict__ B, int ldb, long long sB,
                  float* __restrict__ C, int ldc, long long sC,
                  int K, const float* __restrict__ bias)
{
    const int tid = threadIdx.x;
    const int wid = tid >> 5, lid = tid & 31;
    const int g = lid >> 2, tq = lid & 3;
    const int wm = wid & 1, wn = wid >> 1;     // warps: 2(M) x 2(N)
    const int bx = blockIdx.x, by = blockIdx.y, bz = blockIdx.z;

    A += (long long)bz * sA + (long long)(by * TM) * lda;
    B += (long long)bz * sB + (long long)(bx * TN) * ldb;
    C += (long long)bz * sC + (long long)(by * TM) * ldc + bx * TN;

    const uint32_t sbase = smem_u32(smu);

    // Staging map: 1 thread per row, 16 floats (4 x float4 -> 4 x STS.128)
    const float* Ap = A + (long long)tid * lda;
    const float* Bp = B + (long long)tid * ldb;
    const uint32_t sts_off = (uint32_t)(tid * ROWP) * 4u;

    // ldmatrix lane addressing (byte offsets within a tile)
    //  A frag (m16k8): lanes 0-15 rows 0-15 @k0, lanes 16-31 rows 0-15 @k0+4
    const int laneRowA = lid & 15;
    const int laneColA = (lid >> 4) << 2;
    const uint32_t aLane = (uint32_t)(((wm * 64 + laneRowA) * ROWP + laneColA) * 4);
    //  B frags (two n8k8): lanes 0-7 n0-7@k0, 8-15 n0-7@k0+4, 16-23 n8-15@k0, 24-31 n8-15@k0+4
    const int laneRowB = (lid & 7) | ((lid >> 4) << 3);
    const int laneColB = ((lid >> 3) & 1) << 2;
    const uint32_t bLane = (uint32_t)(((wn * 64 + laneRowB) * ROWP + laneColB) * 4);

    float acc[4][8][4];
    #pragma unroll
    for (int i = 0; i < 4; i++)
        #pragma unroll
        for (int j = 0; j < 8; j++)
            #pragma unroll
            for (int r = 0; r < 4; r++) acc[i][j][r] = 0.f;

    // ---- stage tile 0 into buffer 0 ----
    #pragma unroll
    for (int i = 0; i < 4; i++) {
        float4 va = *(const float4*)(Ap + i * 4);
        float4 vb = *(const float4*)(Bp + i * 4);
        sts128(sbase + sts_off + i * 16,
               f2tf32(va.x), f2tf32(va.y), f2tf32(va.z), f2tf32(va.w));
        sts128(sbase + TILE_BYTES + sts_off + i * 16,
               f2tf32(vb.x), f2tf32(vb.y), f2tf32(vb.z), f2tf32(vb.w));
    }
    __syncthreads();

    const int NK = K / TK;

    for (int t = 0; t < NK; ++t) {
        const int cur = t & 1;
        const uint32_t aBuf = sbase + cur * 2 * TILE_BYTES;
        const uint32_t bBuf = aBuf + TILE_BYTES;

        // prefetch next k-tile from gmem (overlaps with MMAs below)
        const bool more = (t + 1 < NK);
        float4 pa[4], pb[4];
        if (more) {
            const float* An = Ap + (t + 1) * TK;
            const float* Bn = Bp + (t + 1) * TK;
            #pragma unroll
            for (int i = 0; i < 4; i++) {
                pa[i] = *(const float4*)(An + i * 4);
                pb[i] = *(const float4*)(Bn + i * 4);
            }
        }

        // ---- compute: 2 k-steps of k=8, warp tile 64x64 (32 MMAs/step) ----
        #pragma unroll
        for (int ks = 0; ks < 2; ++ks) {
            const uint32_t kOff = (uint32_t)(ks * 8 * 4);
            uint32_t af[4][4], bf[8][2];
            #pragma unroll
            for (int mb = 0; mb < 4; mb++)
                ldsm4(af[mb][0], af[mb][1], af[mb][2], af[mb][3],
                      aBuf + aLane + kOff + (uint32_t)(mb * 16 * ROWP * 4));
            #pragma unroll
            for (int q = 0; q < 4; q++)
                ldsm4(bf[2 * q][0], bf[2 * q][1], bf[2 * q + 1][0], bf[2 * q + 1][1],
                      bBuf + bLane + kOff + (uint32_t)(q * 16 * ROWP * 4));
            #pragma unroll
            for (int mb = 0; mb < 4; mb++)
                #pragma unroll
                for (int nb = 0; nb < 8; nb++)
                    mma16n8k8(acc[mb][nb], af[mb][0], af[mb][1], af[mb][2], af[mb][3],
                              bf[nb][0], bf[nb][1]);
        }

        // ---- stage next tile into the other buffer ----
        if (more) {
            const uint32_t aN = sbase + (cur ^ 1) * 2 * TILE_BYTES;
            #pragma unroll
            for (int i = 0; i < 4; i++) {
                sts128(aN + sts_off + i * 16,
                       f2tf32(pa[i].x), f2tf32(pa[i].y), f2tf32(pa[i].z), f2tf32(pa[i].w));
                sts128(aN + TILE_BYTES + sts_off + i * 16,
                       f2tf32(pb[i].x), f2tf32(pb[i].y), f2tf32(pb[i].z), f2tf32(pb[i].w));
            }
        }
        __syncthreads();
    }

    // ---- epilogue ----
    float badd[8][2];
    #pragma unroll
    for (int nb = 0; nb < 8; nb++) {
        const int col = wn * 64 + nb * 8 + tq * 2;
        badd[nb][0] = bias ? __ldg(bias + bx * TN + col)     : 0.f;
        badd[nb][1] = bias ? __ldg(bias + bx * TN + col + 1) : 0.f;
    }
    #pragma unroll
    for (int mb = 0; mb < 4; mb++) {
        const int row = wm * 64 + mb * 16 + g;
        #pragma unroll
        for (int nb = 0; nb < 8; nb++) {
            const int col = wn * 64 + nb * 8 + tq * 2;
            float2 v0 = make_float2(acc[mb][nb][0] + badd[nb][0],
                                    acc[mb][nb][1] + badd[nb][1]);
            float2 v1 = make_float2(acc[mb][nb][2] + badd[nb][0],
                                    acc[mb][nb][3] + badd[nb][1]);
            *(float2*)(C + (long long)row * ldc + col)       = v0;
            *(float2*)(C + (long long)(row + 8) * ldc + col) = v1;
        }
    }
}

// ---------------------------------------------------------------------------
// Generic 32x32 tiled transpose: out[c][r] = in[r][c], batched.
// ---------------------------------------------------------------------------
__global__ void transpose_f32(const float* __restrict__ in, long long sIn, int ldin,
                              float* __restrict__ out, long long sOut, int ldout)
{
    __shared__ float tile[32][33];
    const int b  = blockIdx.z;
    const int c0 = blockIdx.x << 5;
    const int r0 = blockIdx.y << 5;
    const int x = threadIdx.x, y = threadIdx.y;     // 32 x 8
    const float* ip = in + (long long)b * sIn;
    float* op = out + (long long)b * sOut;
    #pragma unroll
    for (int j = 0; j < 32; j += 8)
        tile[y + j][x] = ip[(long long)(r0 + y + j) * ldin + c0 + x];
    __syncthreads();
    #pragma unroll
    for (int j = 0; j < 32; j += 8)
        op[(long long)(c0 + y + j) * ldout + r0 + x] = tile[x][y + j];
}

// ---------------------------------------------------------------------------
// Row softmax over 4096 columns (scale folded in). Already at DRAM roofline.
// ---------------------------------------------------------------------------
__device__ __forceinline__ float warpMax(float v) {
    #pragma unroll
    for (int o = 16; o > 0; o >>= 1) v = fmaxf(v, __shfl_xor_sync(0xffffffffu, v, o));
    return v;
}
__device__ __forceinline__ float warpSum(float v) {
    #pragma unroll
    for (int o = 16; o > 0; o >>= 1) v += __shfl_xor_sync(0xffffffffu, v, o);
    return v;
}

__global__ __launch_bounds__(256, 4)
void softmax4096(float* __restrict__ s, float scale)
{
    float* p = s + (long long)blockIdx.x * 4096;
    const int t = threadIdx.x;
    const int lane = t & 31, wid = t >> 5;
    __shared__ float red[8];

    float4 v[4];
    #pragma unroll
    for (int i = 0; i < 4; i++) {
        v[i] = *(const float4*)(p + i * 1024 + t * 4);
        v[i].x *= scale; v[i].y *= scale; v[i].z *= scale; v[i].w *= scale;
    }
    float m = v[0].x;
    #pragma unroll
    for (int i = 0; i < 4; i++) {
        m = fmaxf(m, v[i].x); m = fmaxf(m, v[i].y);
        m = fmaxf(m, v[i].z); m = fmaxf(m, v[i].w);
    }
    m = warpMax(m);
    if (lane == 0) red[wid] = m;
    __syncthreads();
    m = red[0];
    #pragma unroll
    for (int j = 1; j < 8; j++) m = fmaxf(m, red[j]);

    float sum = 0.f;
    #pragma unroll
    for (int i = 0; i < 4; i++) {
        v[i].x = expf(v[i].x - m); v[i].y = expf(v[i].y - m);
        v[i].z = expf(v[i].z - m); v[i].w = expf(v[i].w - m);
        sum += v[i].x + v[i].y + v[i].z + v[i].w;
    }
    sum = warpSum(sum);
    __syncthreads();
    if (lane == 0) red[wid] = sum;
    __syncthreads();
    float tot = red[0];
    #pragma unroll
    for (int j = 1; j < 8; j++) tot += red[j];
    const float inv = 1.0f / tot;

    #pragma unroll
    for (int i = 0; i < 4; i++) {
        v[i].x *= inv; v[i].y *= inv; v[i].z *= inv; v[i].w *= inv;
        *(float4*)(p + i * 1024 + t * 4) = v[i];
    }
}

// ---------------------------------------------------------------------------
// Launch
// ---------------------------------------------------------------------------
extern "C" void kernel_launch(void* const* d_in, const int* in_sizes, int n_in,
                              void* d_out, int out_size)
{
    (void)in_sizes; (void)n_in; (void)out_size;
    const float* x = (const float*)d_in[0];   // [B,S,D]
    const float* W = (const float*)d_in[1];   // [D,3D]
    const float* b = (const float*)d_in[2];   // [3D]
    float* out = (float*)d_out;               // [B,S,D]

    float *qkv, *wt, *vt, *sc;
    cudaGetSymbolAddress((void**)&qkv, g_qkv);
    cudaGetSymbolAddress((void**)&wt,  g_wt);
    cudaGetSymbolAddress((void**)&vt,  g_vt);
    cudaGetSymbolAddress((void**)&sc,  g_sc);

    cudaFuncSetAttribute(gemm_tf32mma, cudaFuncAttributeMaxDynamicSharedMemorySize, SMEM_BYTES);

    // 0) Wt[e][d] = W[d][e]
    transpose_f32<<<dim3(3 * DDIM / 32, DDIM / 32, 1), dim3(32, 8)>>>(
        W, 0LL, 3 * DDIM, wt, 0LL, DDIM);

    // 1) qkv = x @ Wt^T + b   (M=16384, N=3072, K=1024)
    gemm_tf32mma<<<dim3(3 * DDIM / TN, BDIM * SDIM / TM, 1), 128, SMEM_BYTES>>>(
        x,   DDIM, 0LL,
        wt,  DDIM, 0LL,
        qkv, 3 * DDIM, 0LL,
        DDIM, b);

    // 2) Vt[b][d][s] = V[b][s][d]
    transpose_f32<<<dim3(DDIM / 32, SDIM / 32, BDIM), dim3(32, 8)>>>(
        qkv + 2 * DDIM, (long long)SDIM * 3 * DDIM, 3 * DDIM,
        vt,             (long long)DDIM * SDIM,     SDIM);

    // 3) scores = Q @ K^T   (per batch: M=4096, N=4096, K=1024)
    gemm_tf32mma<<<dim3(SDIM / TN, SDIM / TM, BDIM), 128, SMEM_BYTES>>>(
        qkv,        3 * DDIM, (long long)SDIM * 3 * DDIM,
        qkv + DDIM, 3 * DDIM, (long long)SDIM * 3 * DDIM,
        sc,         SDIM,     (long long)SDIM * SDIM,
        DDIM, (const float*)0);

    // 4) softmax rows (scale = D^-0.5 = 1/32)
    softmax4096<<<BDIM * SDIM, 256>>>(sc, 0.03125f);

    // 5) out = P @ Vt^T   (per batch: M=4096, N=1024, K=4096)
    gemm_tf32mma<<<dim3(DDIM / TN, SDIM / TM, BDIM), 128, SMEM_BYTES>>>(
        sc,  SDIM, (long long)SDIM * SDIM,
        vt,  SDIM, (long long)DDIM * SDIM,
        out, DDIM, (long long)SDIM * DDIM,
        SDIM, (const float*)0);
}

// round 11
// speedup vs baseline: 1.3274x; 1.2118x over previous
#include <cuda_runtime.h>
#include <stdint.h>
#include <math.h>

#define BDIM 4
#define SDIM 4096
#define DDIM 1024

// Scratch (device globals — allocation-free per harness rules)
__device__ float g_qkv[(size_t)BDIM * SDIM * 3 * DDIM];  // [B*S, 3D]  (tf32-rounded)
__device__ float g_wt [(size_t)3 * DDIM * DDIM];         // W^T [3D, D] (tf32-rounded)
__device__ float g_vt [(size_t)BDIM * DDIM * SDIM];      // V^T [B][D][S] (tf32-rounded)
__device__ float g_sc [(size_t)BDIM * SDIM * SDIM];      // scores/attn (attn tf32-rounded)
__device__ float g_xr [(size_t)BDIM * SDIM * DDIM];      // x rounded to tf32

// ---------------------------------------------------------------------------
// Arch-portable PTX helpers (NO tcgen05 — harness targets sm_103 base)
// ---------------------------------------------------------------------------
__device__ __forceinline__ uint32_t f2tf32(float f) {
    uint32_t r; asm("cvt.rna.tf32.f32 %0, %1;" : "=r"(r) : "f"(f)); return r;
}
__device__ __forceinline__ float roundtf(float f) { return __uint_as_float(f2tf32(f)); }
__device__ __forceinline__ uint32_t smem_u32(const void* p) {
    uint32_t a;
    asm("{ .reg .u64 t; cvta.to.shared.u64 t, %1; cvt.u32.u64 %0, t; }" : "=r"(a) : "l"(p));
    return a;
}
__device__ __forceinline__ void mma16n8k8(float c[4],
                                          uint32_t a0, uint32_t a1, uint32_t a2, uint32_t a3,
                                          uint32_t b0, uint32_t b1) {
    asm volatile(
        "mma.sync.aligned.m16n8k8.row.col.f32.tf32.tf32.f32 "
        "{%0,%1,%2,%3}, {%4,%5,%6,%7}, {%8,%9}, {%0,%1,%2,%3};"
        : "+f"(c[0]), "+f"(c[1]), "+f"(c[2]), "+f"(c[3])
        : "r"(a0), "r"(a1), "r"(a2), "r"(a3), "r"(b0), "r"(b1));
}
__device__ __forceinline__ void ldsm4(uint32_t& r0, uint32_t& r1, uint32_t& r2, uint32_t& r3,
                                      uint32_t addr) {
    asm volatile("ldmatrix.sync.aligned.m8n8.x4.shared.b16 {%0,%1,%2,%3}, [%4];"
                 : "=r"(r0), "=r"(r1), "=r"(r2), "=r"(r3) : "r"(addr));
}
__device__ __forceinline__ void cpasync16(uint32_t s, const void* g) {
    asm volatile("cp.async.cg.shared.global [%0], [%1], 16;" :: "r"(s), "l"(g));
}
__device__ __forceinline__ void cp_commit() {
    asm volatile("cp.async.commit_group;" ::: "memory");
}
__device__ __forceinline__ void cp_wait2() {
    asm volatile("cp.async.wait_group 2;" ::: "memory");
}

// ---------------------------------------------------------------------------
// TN tf32 GEMM: C[M,N] = A[M,K] @ B[N,K]^T (+ bias). A,B already tf32-rounded.
// CTA 128x128x16, 128 threads (4 warps = 2M x 2N, warp tile 64x64), 2 CTA/SM.
// 4-stage cp.async pipeline gmem->smem (no register staging, no cvt in loop).
// ROWP=20 floats: cp.async 16B writes and LDSM 8-row fetches cover all banks.
// ---------------------------------------------------------------------------
#define TM 128
#define TN 128
#define TK 16
#define ROWP 20
#define TILE_BYTES (128 * ROWP * 4)           // 10240 B per operand tile
#define NSTAGE 4
#define SMEM_BYTES (NSTAGE * 2 * TILE_BYTES)  // 81920 B

extern __shared__ uint32_t smu[];

__global__ __launch_bounds__(128, 2)
void gemm_tf32mma(const float* __restrict__ A, int lda, long long sA,
                  const float* __restrict__ B, int ldb, long long sB,
                  float* __restrict__ C, int ldc, long long sC,
                  int K, const float* __restrict__ bias, int roundC)
{
    const int tid = threadIdx.x;
    const int wid = tid >> 5, lid = tid & 31;
    const int g = lid >> 2, tq = lid & 3;
    const int wm = wid & 1, wn = wid >> 1;     // warps: 2(M) x 2(N)
    const int bx = blockIdx.x, by = blockIdx.y, bz = blockIdx.z;

    A += (long long)bz * sA + (long long)(by * TM) * lda;
    B += (long long)bz * sB + (long long)(bx * TN) * ldb;
    C += (long long)bz * sC + (long long)(by * TM) * ldc + bx * TN;

    const uint32_t sbase = smem_u32(smu);

    // Copy map: 1 thread per row, 16 floats (4 x cp.async 16B) per operand
    const float* Ap = A + (long long)tid * lda;
    const float* Bp = B + (long long)tid * ldb;
    const uint32_t sts_off = (uint32_t)(tid * ROWP) * 4u;

    // ldmatrix lane addressing (byte offsets within a tile)
    const int laneRowA = lid & 15;
    const int laneColA = (lid >> 4) << 2;
    const uint32_t aLane = (uint32_t)(((wm * 64 + laneRowA) * ROWP + laneColA) * 4);
    const int laneRowB = (lid & 7) | ((lid >> 4) << 3);
    const int laneColB = ((lid >> 3) & 1) << 2;
    const uint32_t bLane = (uint32_t)(((wn * 64 + laneRowB) * ROWP + laneColB) * 4);

    float acc[4][8][4];
    #pragma unroll
    for (int i = 0; i < 4; i++)
        #pragma unroll
        for (int j = 0; j < 8; j++)
            #pragma unroll
            for (int r = 0; r < 4; r++) acc[i][j][r] = 0.f;

    const int NK = K / TK;

    auto stage_copy = [&](int t) {
        const uint32_t dst = sbase + (uint32_t)(t & (NSTAGE - 1)) * 2 * TILE_BYTES;
        const float* As = Ap + t * TK;
        const float* Bs = Bp + t * TK;
        #pragma unroll
        for (int i = 0; i < 4; i++) cpasync16(dst + sts_off + i * 16, As + i * 4);
        #pragma unroll
        for (int i = 0; i < 4; i++) cpasync16(dst + TILE_BYTES + sts_off + i * 16, Bs + i * 4);
    };

    // ---- prologue: fill 3 stages ----
    #pragma unroll
    for (int p = 0; p < NSTAGE - 1; p++) { stage_copy(p); cp_commit(); }
    cp_wait2();
    __syncthreads();

    for (int t = 0; t < NK; ++t) {
        if (t + NSTAGE - 1 < NK) stage_copy(t + NSTAGE - 1);
        cp_commit();

        const uint32_t aBuf = sbase + (uint32_t)(t & (NSTAGE - 1)) * 2 * TILE_BYTES;
        const uint32_t bBuf = aBuf + TILE_BYTES;

        // ---- compute: 2 k-steps of k=8, warp tile 64x64 (32 MMAs/step) ----
        #pragma unroll
        for (int ks = 0; ks < 2; ++ks) {
            const uint32_t kOff = (uint32_t)(ks * 8 * 4);
            uint32_t af[4][4], bf[8][2];
            #pragma unroll
            for (int mb = 0; mb < 4; mb++)
                ldsm4(af[mb][0], af[mb][1], af[mb][2], af[mb][3],
                      aBuf + aLane + kOff + (uint32_t)(mb * 16 * ROWP * 4));
            #pragma unroll
            for (int q = 0; q < 4; q++)
                ldsm4(bf[2 * q][0], bf[2 * q][1], bf[2 * q + 1][0], bf[2 * q + 1][1],
                      bBuf + bLane + kOff + (uint32_t)(q * 16 * ROWP * 4));
            #pragma unroll
            for (int mb = 0; mb < 4; mb++)
                #pragma unroll
                for (int nb = 0; nb < 8; nb++)
                    mma16n8k8(acc[mb][nb], af[mb][0], af[mb][1], af[mb][2], af[mb][3],
                              bf[nb][0], bf[nb][1]);
        }

        cp_wait2();
        __syncthreads();
    }

    // ---- epilogue ----
    float badd[8][2];
    #pragma unroll
    for (int nb = 0; nb < 8; nb++) {
        const int col = wn * 64 + nb * 8 + tq * 2;
        badd[nb][0] = bias ? __ldg(bias + bx * TN + col)     : 0.f;
        badd[nb][1] = bias ? __ldg(bias + bx * TN + col + 1) : 0.f;
    }
    #pragma unroll
    for (int mb = 0; mb < 4; mb++) {
        const int row = wm * 64 + mb * 16 + g;
        #pragma unroll
        for (int nb = 0; nb < 8; nb++) {
            const int col = wn * 64 + nb * 8 + tq * 2;
            float o0 = acc[mb][nb][0] + badd[nb][0];
            float o1 = acc[mb][nb][1] + badd[nb][1];
            float o2 = acc[mb][nb][2] + badd[nb][0];
            float o3 = acc[mb][nb][3] + badd[nb][1];
            if (roundC) { o0 = roundtf(o0); o1 = roundtf(o1); o2 = roundtf(o2); o3 = roundtf(o3); }
            *(float2*)(C + (long long)row * ldc + col)       = make_float2(o0, o1);
            *(float2*)(C + (long long)(row + 8) * ldc + col) = make_float2(o2, o3);
        }
    }
}

// ---------------------------------------------------------------------------
// Elementwise round-to-tf32 (for x). Grid-stride float4.
// ---------------------------------------------------------------------------
__global__ void round_tf32_kernel(const float* __restrict__ in, float* __restrict__ out,
                                  size_t n4)
{
    size_t i = (size_t)blockIdx.x * blockDim.x + threadIdx.x;
    size_t stride = (size_t)gridDim.x * blockDim.x;
    for (; i < n4; i += stride) {
        float4 v = ((const float4*)in)[i];
        v.x = roundtf(v.x); v.y = roundtf(v.y); v.z = roundtf(v.z); v.w = roundtf(v.w);
        ((float4*)out)[i] = v;
    }
}

// ---------------------------------------------------------------------------
// Generic 32x32 tiled transpose (tf32-rounds its output), batched.
// ---------------------------------------------------------------------------
__global__ void transpose_f32(const float* __restrict__ in, long long sIn, int ldin,
                              float* __restrict__ out, long long sOut, int ldout)
{
    __shared__ float tile[32][33];
    const int b  = blockIdx.z;
    const int c0 = blockIdx.x << 5;
    const int r0 = blockIdx.y << 5;
    const int x = threadIdx.x, y = threadIdx.y;     // 32 x 8
    const float* ip = in + (long long)b * sIn;
    float* op = out + (long long)b * sOut;
    #pragma unroll
    for (int j = 0; j < 32; j += 8)
        tile[y + j][x] = ip[(long long)(r0 + y + j) * ldin + c0 + x];
    __syncthreads();
    #pragma unroll
    for (int j = 0; j < 32; j += 8)
        op[(long long)(c0 + y + j) * ldout + r0 + x] = roundtf(tile[x][y + j]);
}

// ---------------------------------------------------------------------------
// Row softmax over 4096 columns; writes tf32-rounded probabilities.
// ---------------------------------------------------------------------------
__device__ __forceinline__ float warpMax(float v) {
    #pragma unroll
    for (int o = 16; o > 0; o >>= 1) v = fmaxf(v, __shfl_xor_sync(0xffffffffu, v, o));
    return v;
}
__device__ __forceinline__ float warpSum(float v) {
    #pragma unroll
    for (int o = 16; o > 0; o >>= 1) v += __shfl_xor_sync(0xffffffffu, v, o);
    return v;
}

__global__ __launch_bounds__(256, 4)
void softmax4096(float* __restrict__ s, float scale)
{
    float* p = s + (long long)blockIdx.x * 4096;
    const int t = threadIdx.x;
    const int lane = t & 31, wid = t >> 5;
    __shared__ float red[8];

    float4 v[4];
    #pragma unroll
    for (int i = 0; i < 4; i++) {
        v[i] = *(const float4*)(p + i * 1024 + t * 4);
        v[i].x *= scale; v[i].y *= scale; v[i].z *= scale; v[i].w *= scale;
    }
    float m = v[0].x;
    #pragma unroll
    for (int i = 0; i < 4; i++) {
        m = fmaxf(m, v[i].x); m = fmaxf(m, v[i].y);
        m = fmaxf(m, v[i].z); m = fmaxf(m, v[i].w);
    }
    m = warpMax(m);
    if (lane == 0) red[wid] = m;
    __syncthreads();
    m = red[0];
    #pragma unroll
    for (int j = 1; j < 8; j++) m = fmaxf(m, red[j]);

    float sum = 0.f;
    #pragma unroll
    for (int i = 0; i < 4; i++) {
        v[i].x = expf(v[i].x - m); v[i].y = expf(v[i].y - m);
        v[i].z = expf(v[i].z - m); v[i].w = expf(v[i].w - m);
        sum += v[i].x + v[i].y + v[i].z + v[i].w;
    }
    sum = warpSum(sum);
    __syncthreads();
    if (lane == 0) red[wid] = sum;
    __syncthreads();
    float tot = red[0];
    #pragma unroll
    for (int j = 1; j < 8; j++) tot += red[j];
    const float inv = 1.0f / tot;

    #pragma unroll
    for (int i = 0; i < 4; i++) {
        v[i].x = roundtf(v[i].x * inv); v[i].y = roundtf(v[i].y * inv);
        v[i].z = roundtf(v[i].z * inv); v[i].w = roundtf(v[i].w * inv);
        *(float4*)(p + i * 1024 + t * 4) = v[i];
    }
}

// ---------------------------------------------------------------------------
// Launch
// ---------------------------------------------------------------------------
extern "C" void kernel_launch(void* const* d_in, const int* in_sizes, int n_in,
                              void* d_out, int out_size)
{
    (void)in_sizes; (void)n_in; (void)out_size;
    const float* x = (const float*)d_in[0];   // [B,S,D]
    const float* W = (const float*)d_in[1];   // [D,3D]
    const float* b = (const float*)d_in[2];   // [3D]
    float* out = (float*)d_out;               // [B,S,D]

    float *qkv, *wt, *vt, *sc, *xr;
    cudaGetSymbolAddress((void**)&qkv, g_qkv);
    cudaGetSymbolAddress((void**)&wt,  g_wt);
    cudaGetSymbolAddress((void**)&vt,  g_vt);
    cudaGetSymbolAddress((void**)&sc,  g_sc);
    cudaGetSymbolAddress((void**)&xr,  g_xr);

    cudaFuncSetAttribute(gemm_tf32mma, cudaFuncAttributeMaxDynamicSharedMemorySize, SMEM_BYTES);

    // 0a) xr = round_tf32(x)
    round_tf32_kernel<<<1024, 256>>>(x, xr, (size_t)BDIM * SDIM * DDIM / 4);

    // 0b) Wt[e][d] = round_tf32(W[d][e])
    transpose_f32<<<dim3(3 * DDIM / 32, DDIM / 32, 1), dim3(32, 8)>>>(
        W, 0LL, 3 * DDIM, wt, 0LL, DDIM);

    // 1) qkv = round_tf32(xr @ Wt^T + b)   (M=16384, N=3072, K=1024)
    gemm_tf32mma<<<dim3(3 * DDIM / TN, BDIM * SDIM / TM, 1), 128, SMEM_BYTES>>>(
        xr,  DDIM, 0LL,
        wt,  DDIM, 0LL,
        qkv, 3 * DDIM, 0LL,
        DDIM, b, 1);

    // 2) Vt[b][d][s] = V[b][s][d]   (already tf32; transpose re-round is no-op)
    transpose_f32<<<dim3(DDIM / 32, SDIM / 32, BDIM), dim3(32, 8)>>>(
        qkv + 2 * DDIM, (long long)SDIM * 3 * DDIM, 3 * DDIM,
        vt,             (long long)DDIM * SDIM,     SDIM);

    // 3) scores = Q @ K^T   (per batch: M=4096, N=4096, K=1024)
    gemm_tf32mma<<<dim3(SDIM / TN, SDIM / TM, BDIM), 128, SMEM_BYTES>>>(
        qkv,        3 * DDIM, (long long)SDIM * 3 * DDIM,
        qkv + DDIM, 3 * DDIM, (long long)SDIM * 3 * DDIM,
        sc,         SDIM,     (long long)SDIM * SDIM,
        DDIM, (const float*)0, 0);

    // 4) softmax rows (scale = D^-0.5 = 1/32), writes tf32-rounded attn
    softmax4096<<<BDIM * SDIM, 256>>>(sc, 0.03125f);

    // 5) out = P @ Vt^T   (per batch: M=4096, N=1024, K=4096) — NOT rounded
    gemm_tf32mma<<<dim3(DDIM / TN, SDIM / TM, BDIM), 128, SMEM_BYTES>>>(
        sc,  SDIM, (long long)SDIM * SDIM,
        vt,  SDIM, (long long)DDIM * SDIM,
        out, DDIM, (long long)SDIM * DDIM,
        SDIM, (const float*)0, 0);
}

// round 12
// speedup vs baseline: 1.3940x; 1.0502x over previous
#include <cuda_runtime.h>
#include <stdint.h>
#include <math.h>

#define BDIM 4
#define SDIM 4096
#define DDIM 1024

// Scratch (device globals — allocation-free per harness rules)
__device__ float g_qkv[(size_t)BDIM * SDIM * 3 * DDIM];  // [B*S, 3D]  (tf32-rounded)
__device__ float g_wt [(size_t)3 * DDIM * DDIM];         // W^T [3D, D] (tf32-rounded)
__device__ float g_vt [(size_t)BDIM * DDIM * SDIM];      // V^T [B][D][S] (tf32-rounded)
__device__ float g_sc [(size_t)BDIM * SDIM * SDIM];      // scores/attn (attn tf32-rounded)
__device__ float g_xr [(size_t)BDIM * SDIM * DDIM];      // x rounded to tf32

// ---------------------------------------------------------------------------
// Arch-portable PTX helpers (NO tcgen05 — harness targets sm_103 base)
// ---------------------------------------------------------------------------
__device__ __forceinline__ uint32_t f2tf32(float f) {
    uint32_t r; asm("cvt.rna.tf32.f32 %0, %1;" : "=r"(r) : "f"(f)); return r;
}
__device__ __forceinline__ float roundtf(float f) { return __uint_as_float(f2tf32(f)); }
__device__ __forceinline__ uint32_t smem_u32(const void* p) {
    uint32_t a;
    asm("{ .reg .u64 t; cvta.to.shared.u64 t, %1; cvt.u32.u64 %0, t; }" : "=r"(a) : "l"(p));
    return a;
}
__device__ __forceinline__ void mma16n8k8(float c[4],
                                          uint32_t a0, uint32_t a1, uint32_t a2, uint32_t a3,
                                          uint32_t b0, uint32_t b1) {
    asm volatile(
        "mma.sync.aligned.m16n8k8.row.col.f32.tf32.tf32.f32 "
        "{%0,%1,%2,%3}, {%4,%5,%6,%7}, {%8,%9}, {%0,%1,%2,%3};"
        : "+f"(c[0]), "+f"(c[1]), "+f"(c[2]), "+f"(c[3])
        : "r"(a0), "r"(a1), "r"(a2), "r"(a3), "r"(b0), "r"(b1));
}
__device__ __forceinline__ void ldsm4(uint32_t& r0, uint32_t& r1, uint32_t& r2, uint32_t& r3,
                                      uint32_t addr) {
    asm volatile("ldmatrix.sync.aligned.m8n8.x4.shared.b16 {%0,%1,%2,%3}, [%4];"
                 : "=r"(r0), "=r"(r1), "=r"(r2), "=r"(r3) : "r"(addr));
}
__device__ __forceinline__ void cpasync16(uint32_t s, const void* g) {
    asm volatile("cp.async.cg.shared.global [%0], [%1], 16;" :: "r"(s), "l"(g));
}
__device__ __forceinline__ void cp_commit() {
    asm volatile("cp.async.commit_group;" ::: "memory");
}
__device__ __forceinline__ void cp_wait2() {
    asm volatile("cp.async.wait_group 2;" ::: "memory");
}

// ---------------------------------------------------------------------------
// TN tf32 GEMM: C[M,N] = A[M,K] @ B[N,K]^T (+ bias). A,B already tf32-rounded.
// CTA 128x128x16, 128 threads (4 warps = 2M x 2N, warp tile 64x64), 2 CTA/SM.
// 4-stage cp.async gmem->smem pipeline + register double-buffered fragments:
// LDSM for k-step s+1 issues before the MMAs of k-step s, keeping the tensor
// pipe fed across k-steps AND across the stage barrier.
// ---------------------------------------------------------------------------
#define TM 128
#define TN 128
#define TK 16
#define ROWP 20
#define TILE_BYTES (128 * ROWP * 4)           // 10240 B per operand tile
#define NSTAGE 4
#define SMEM_BYTES (NSTAGE * 2 * TILE_BYTES)  // 81920 B

extern __shared__ uint32_t smu[];

__device__ __forceinline__ void load_frags(uint32_t aBuf, uint32_t bBuf, uint32_t kOff,
                                           uint32_t aLane, uint32_t bLane,
                                           uint32_t af[4][4], uint32_t bf[8][2])
{
    #pragma unroll
    for (int mb = 0; mb < 4; mb++)
        ldsm4(af[mb][0], af[mb][1], af[mb][2], af[mb][3],
              aBuf + aLane + kOff + (uint32_t)(mb * 16 * ROWP * 4));
    #pragma unroll
    for (int q = 0; q < 4; q++)
        ldsm4(bf[2 * q][0], bf[2 * q][1], bf[2 * q + 1][0], bf[2 * q + 1][1],
              bBuf + bLane + kOff + (uint32_t)(q * 16 * ROWP * 4));
}

__device__ __forceinline__ void do_mmas(float acc[4][8][4],
                                        uint32_t af[4][4], uint32_t bf[8][2])
{
    #pragma unroll
    for (int mb = 0; mb < 4; mb++)
        #pragma unroll
        for (int nb = 0; nb < 8; nb++)
            mma16n8k8(acc[mb][nb], af[mb][0], af[mb][1], af[mb][2], af[mb][3],
                      bf[nb][0], bf[nb][1]);
}

__global__ __launch_bounds__(128, 2)
void gemm_tf32mma(const float* __restrict__ A, int lda, long long sA,
                  const float* __restrict__ B, int ldb, long long sB,
                  float* __restrict__ C, int ldc, long long sC,
                  int K, const float* __restrict__ bias, int roundC)
{
    const int tid = threadIdx.x;
    const int wid = tid >> 5, lid = tid & 31;
    const int g = lid >> 2, tq = lid & 3;
    const int wm = wid & 1, wn = wid >> 1;     // warps: 2(M) x 2(N)
    const int bx = blockIdx.x, by = blockIdx.y, bz = blockIdx.z;

    A += (long long)bz * sA + (long long)(by * TM) * lda;
    B += (long long)bz * sB + (long long)(bx * TN) * ldb;
    C += (long long)bz * sC + (long long)(by * TM) * ldc + bx * TN;

    const uint32_t sbase = smem_u32(smu);

    // Copy map: 1 thread per row, 16 floats (4 x cp.async 16B) per operand
    const float* Ap = A + (long long)tid * lda;
    const float* Bp = B + (long long)tid * ldb;
    const uint32_t sts_off = (uint32_t)(tid * ROWP) * 4u;

    // ldmatrix lane addressing (byte offsets within a tile)
    const int laneRowA = lid & 15;
    const int laneColA = (lid >> 4) << 2;
    const uint32_t aLane = (uint32_t)(((wm * 64 + laneRowA) * ROWP + laneColA) * 4);
    const int laneRowB = (lid & 7) | ((lid >> 4) << 3);
    const int laneColB = ((lid >> 3) & 1) << 2;
    const uint32_t bLane = (uint32_t)(((wn * 64 + laneRowB) * ROWP + laneColB) * 4);

    float acc[4][8][4];
    #pragma unroll
    for (int i = 0; i < 4; i++)
        #pragma unroll
        for (int j = 0; j < 8; j++)
            #pragma unroll
            for (int r = 0; r < 4; r++) acc[i][j][r] = 0.f;

    const int NK = K / TK;

    auto stage_copy = [&](int t) {
        const uint32_t dst = sbase + (uint32_t)(t & (NSTAGE - 1)) * 2 * TILE_BYTES;
        const float* As = Ap + t * TK;
        const float* Bs = Bp + t * TK;
        #pragma unroll
        for (int i = 0; i < 4; i++) cpasync16(dst + sts_off + i * 16, As + i * 4);
        #pragma unroll
        for (int i = 0; i < 4; i++) cpasync16(dst + TILE_BYTES + sts_off + i * 16, Bs + i * 4);
    };

    // ---- prologue: fill 3 stages ----
    #pragma unroll
    for (int p = 0; p < NSTAGE - 1; p++) { stage_copy(p); cp_commit(); }
    cp_wait2();                     // stage 0 guaranteed resident
    __syncthreads();

    // Register-double-buffered fragments
    uint32_t af[2][4][4], bf[2][8][2];
    load_frags(sbase, sbase + TILE_BYTES, 0, aLane, bLane, af[0], bf[0]);

    for (int t = 0; t < NK; ++t) {
        if (t + NSTAGE - 1 < NK) stage_copy(t + NSTAGE - 1);
        cp_commit();

        const uint32_t aBuf = sbase + (uint32_t)(t & (NSTAGE - 1)) * 2 * TILE_BYTES;
        const uint32_t bBuf = aBuf + TILE_BYTES;

        // load ks=1 fragments, then run ks=0 MMAs (LDSM latency hidden by MMAs)
        load_frags(aBuf, bBuf, 8 * 4, aLane, bLane, af[1], bf[1]);
        do_mmas(acc, af[0], bf[0]);

        // make next stage resident; all reads of the overwritten stage are done
        cp_wait2();
        __syncthreads();

        // prefetch next tile's ks=0 fragments, then run ks=1 MMAs
        if (t + 1 < NK) {
            const uint32_t aN = sbase + (uint32_t)((t + 1) & (NSTAGE - 1)) * 2 * TILE_BYTES;
            load_frags(aN, aN + TILE_BYTES, 0, aLane, bLane, af[0], bf[0]);
        }
        do_mmas(acc, af[1], bf[1]);
    }

    // ---- epilogue ----
    float badd[8][2];
    #pragma unroll
    for (int nb = 0; nb < 8; nb++) {
        const int col = wn * 64 + nb * 8 + tq * 2;
        badd[nb][0] = bias ? __ldg(bias + bx * TN + col)     : 0.f;
        badd[nb][1] = bias ? __ldg(bias + bx * TN + col + 1) : 0.f;
    }
    #pragma unroll
    for (int mb = 0; mb < 4; mb++) {
        const int row = wm * 64 + mb * 16 + g;
        #pragma unroll
        for (int nb = 0; nb < 8; nb++) {
            const int col = wn * 64 + nb * 8 + tq * 2;
            float o0 = acc[mb][nb][0] + badd[nb][0];
            float o1 = acc[mb][nb][1] + badd[nb][1];
            float o2 = acc[mb][nb][2] + badd[nb][0];
            float o3 = acc[mb][nb][3] + badd[nb][1];
            if (roundC) { o0 = roundtf(o0); o1 = roundtf(o1); o2 = roundtf(o2); o3 = roundtf(o3); }
            *(float2*)(C + (long long)row * ldc + col)       = make_float2(o0, o1);
            *(float2*)(C + (long long)(row + 8) * ldc + col) = make_float2(o2, o3);
        }
    }
}

// ---------------------------------------------------------------------------
// Elementwise round-to-tf32 (for x). Grid-stride float4.
// ---------------------------------------------------------------------------
__global__ void round_tf32_kernel(const float* __restrict__ in, float* __restrict__ out,
                                  size_t n4)
{
    size_t i = (size_t)blockIdx.x * blockDim.x + threadIdx.x;
    size_t stride = (size_t)gridDim.x * blockDim.x;
    for (; i < n4; i += stride) {
        float4 v = ((const float4*)in)[i];
        v.x = roundtf(v.x); v.y = roundtf(v.y); v.z = roundtf(v.z); v.w = roundtf(v.w);
        ((float4*)out)[i] = v;
    }
}

// ---------------------------------------------------------------------------
// Generic 32x32 tiled transpose (tf32-rounds its output), batched.
// ---------------------------------------------------------------------------
__global__ void transpose_f32(const float* __restrict__ in, long long sIn, int ldin,
                              float* __restrict__ out, long long sOut, int ldout)
{
    __shared__ float tile[32][33];
    const int b  = blockIdx.z;
    const int c0 = blockIdx.x << 5;
    const int r0 = blockIdx.y << 5;
    const int x = threadIdx.x, y = threadIdx.y;     // 32 x 8
    const float* ip = in + (long long)b * sIn;
    float* op = out + (long long)b * sOut;
    #pragma unroll
    for (int j = 0; j < 32; j += 8)
        tile[y + j][x] = ip[(long long)(r0 + y + j) * ldin + c0 + x];
    __syncthreads();
    #pragma unroll
    for (int j = 0; j < 32; j += 8)
        op[(long long)(c0 + y + j) * ldout + r0 + x] = roundtf(tile[x][y + j]);
}

// ---------------------------------------------------------------------------
// Row softmax over 4096 columns; writes tf32-rounded probabilities.
// ---------------------------------------------------------------------------
__device__ __forceinline__ float warpMax(float v) {
    #pragma unroll
    for (int o = 16; o > 0; o >>= 1) v = fmaxf(v, __shfl_xor_sync(0xffffffffu, v, o));
    return v;
}
__device__ __forceinline__ float warpSum(float v) {
    #pragma unroll
    for (int o = 16; o > 0; o >>= 1) v += __shfl_xor_sync(0xffffffffu, v, o);
    return v;
}

__global__ __launch_bounds__(256, 4)
void softmax4096(float* __restrict__ s, float scale)
{
    float* p = s + (long long)blockIdx.x * 4096;
    const int t = threadIdx.x;
    const int lane = t & 31, wid = t >> 5;
    __shared__ float red[8];

    float4 v[4];
    #pragma unroll
    for (int i = 0; i < 4; i++) {
        v[i] = *(const float4*)(p + i * 1024 + t * 4);
        v[i].x *= scale; v[i].y *= scale; v[i].z *= scale; v[i].w *= scale;
    }
    float m = v[0].x;
    #pragma unroll
    for (int i = 0; i < 4; i++) {
        m = fmaxf(m, v[i].x); m = fmaxf(m, v[i].y);
        m = fmaxf(m, v[i].z); m = fmaxf(m, v[i].w);
    }
    m = warpMax(m);
    if (lane == 0) red[wid] = m;
    __syncthreads();
    m = red[0];
    #pragma unroll
    for (int j = 1; j < 8; j++) m = fmaxf(m, red[j]);

    float sum = 0.f;
    #pragma unroll
    for (int i = 0; i < 4; i++) {
        v[i].x = expf(v[i].x - m); v[i].y = expf(v[i].y - m);
        v[i].z = expf(v[i].z - m); v[i].w = expf(v[i].w - m);
        sum += v[i].x + v[i].y + v[i].z + v[i].w;
    }
    sum = warpSum(sum);
    __syncthreads();
    if (lane == 0) red[wid] = sum;
    __syncthreads();
    float tot = red[0];
    #pragma unroll
    for (int j = 1; j < 8; j++) tot += red[j];
    const float inv = 1.0f / tot;

    #pragma unroll
    for (int i = 0; i < 4; i++) {
        v[i].x = roundtf(v[i].x * inv); v[i].y = roundtf(v[i].y * inv);
        v[i].z = roundtf(v[i].z * inv); v[i].w = roundtf(v[i].w * inv);
        *(float4*)(p + i * 1024 + t * 4) = v[i];
    }
}

// ---------------------------------------------------------------------------
// Launch
// ---------------------------------------------------------------------------
extern "C" void kernel_launch(void* const* d_in, const int* in_sizes, int n_in,
                              void* d_out, int out_size)
{
    (void)in_sizes; (void)n_in; (void)out_size;
    const float* x = (const float*)d_in[0];   // [B,S,D]
    const float* W = (const float*)d_in[1];   // [D,3D]
    const float* b = (const float*)d_in[2];   // [3D]
    float* out = (float*)d_out;               // [B,S,D]

    float *qkv, *wt, *vt, *sc, *xr;
    cudaGetSymbolAddress((void**)&qkv, g_qkv);
    cudaGetSymbolAddress((void**)&wt,  g_wt);
    cudaGetSymbolAddress((void**)&vt,  g_vt);
    cudaGetSymbolAddress((void**)&sc,  g_sc);
    cudaGetSymbolAddress((void**)&xr,  g_xr);

    cudaFuncSetAttribute(gemm_tf32mma, cudaFuncAttributeMaxDynamicSharedMemorySize, SMEM_BYTES);

    // 0a) xr = round_tf32(x)
    round_tf32_kernel<<<1024, 256>>>(x, xr, (size_t)BDIM * SDIM * DDIM / 4);

    // 0b) Wt[e][d] = round_tf32(W[d][e])
    transpose_f32<<<dim3(3 * DDIM / 32, DDIM / 32, 1), dim3(32, 8)>>>(
        W, 0LL, 3 * DDIM, wt, 0LL, DDIM);

    // 1) qkv = round_tf32(xr @ Wt^T + b)   (M=16384, N=3072, K=1024)
    gemm_tf32mma<<<dim3(3 * DDIM / TN, BDIM * SDIM / TM, 1), 128, SMEM_BYTES>>>(
        xr,  DDIM, 0LL,
        wt,  DDIM, 0LL,
        qkv, 3 * DDIM, 0LL,
        DDIM, b, 1);

    // 2) Vt[b][d][s] = V[b][s][d]   (already tf32; transpose re-round is no-op)
    transpose_f32<<<dim3(DDIM / 32, SDIM / 32, BDIM), dim3(32, 8)>>>(
        qkv + 2 * DDIM, (long long)SDIM * 3 * DDIM, 3 * DDIM,
        vt,             (long long)DDIM * SDIM,     SDIM);

    // 3) scores = Q @ K^T   (per batch: M=4096, N=4096, K=1024)
    gemm_tf32mma<<<dim3(SDIM / TN, SDIM / TM, BDIM), 128, SMEM_BYTES>>>(
        qkv,        3 * DDIM, (long long)SDIM * 3 * DDIM,
        qkv + DDIM, 3 * DDIM, (long long)SDIM * 3 * DDIM,
        sc,         SDIM,     (long long)SDIM * SDIM,
        DDIM, (const float*)0, 0);

    // 4) softmax rows (scale = D^-0.5 = 1/32), writes tf32-rounded attn
    softmax4096<<<BDIM * SDIM, 256>>>(sc, 0.03125f);

    // 5) out = P @ Vt^T   (per batch: M=4096, N=1024, K=4096) — NOT rounded
    gemm_tf32mma<<<dim3(DDIM / TN, SDIM / TM, BDIM), 128, SMEM_BYTES>>>(
        sc,  SDIM, (long long)SDIM * SDIM,
        vt,  SDIM, (long long)DDIM * SDIM,
        out, DDIM, (long long)SDIM * DDIM,
        SDIM, (const float*)0, 0);
}

// round 13
// speedup vs baseline: 1.4145x; 1.0147x over previous
#include <cuda_runtime.h>
#include <stdint.h>
#include <math.h>

#define BDIM 4
#define SDIM 4096
#define DDIM 1024

// Scratch (device globals — allocation-free per harness rules)
__device__ float g_qkv[(size_t)BDIM * SDIM * 3 * DDIM];  // [B*S, 3D]  (tf32-rounded)
__device__ float g_wt [(size_t)3 * DDIM * DDIM];         // W^T [3D, D] (tf32-rounded)
__device__ float g_vt [(size_t)BDIM * DDIM * SDIM];      // V^T [B][D][S] (tf32-rounded)
__device__ float g_sc [(size_t)BDIM * SDIM * SDIM];      // scores/attn (attn tf32-rounded)
__device__ float g_xr [(size_t)BDIM * SDIM * DDIM];      // x rounded to tf32

// ---------------------------------------------------------------------------
// Arch-portable PTX helpers (NO tcgen05 — harness targets sm_103 base)
// ---------------------------------------------------------------------------
__device__ __forceinline__ uint32_t f2tf32(float f) {
    uint32_t r; asm("cvt.rna.tf32.f32 %0, %1;" : "=r"(r) : "f"(f)); return r;
}
__device__ __forceinline__ float roundtf(float f) { return __uint_as_float(f2tf32(f)); }
__device__ __forceinline__ uint32_t smem_u32(const void* p) {
    uint32_t a;
    asm("{ .reg .u64 t; cvta.to.shared.u64 t, %1; cvt.u32.u64 %0, t; }" : "=r"(a) : "l"(p));
    return a;
}
__device__ __forceinline__ void mma16n8k8(float c[4],
                                          uint32_t a0, uint32_t a1, uint32_t a2, uint32_t a3,
                                          uint32_t b0, uint32_t b1) {
    asm volatile(
        "mma.sync.aligned.m16n8k8.row.col.f32.tf32.tf32.f32 "
        "{%0,%1,%2,%3}, {%4,%5,%6,%7}, {%8,%9}, {%0,%1,%2,%3};"
        : "+f"(c[0]), "+f"(c[1]), "+f"(c[2]), "+f"(c[3])
        : "r"(a0), "r"(a1), "r"(a2), "r"(a3), "r"(b0), "r"(b1));
}
__device__ __forceinline__ void ldsm4(uint32_t& r0, uint32_t& r1, uint32_t& r2, uint32_t& r3,
                                      uint32_t addr) {
    asm volatile("ldmatrix.sync.aligned.m8n8.x4.shared.b16 {%0,%1,%2,%3}, [%4];"
                 : "=r"(r0), "=r"(r1), "=r"(r2), "=r"(r3) : "r"(addr));
}
__device__ __forceinline__ void cpasync16(uint32_t s, const void* g) {
    asm volatile("cp.async.cg.shared.global [%0], [%1], 16;" :: "r"(s), "l"(g));
}
__device__ __forceinline__ void cp_commit() {
    asm volatile("cp.async.commit_group;" ::: "memory");
}
__device__ __forceinline__ void cp_wait1() {
    asm volatile("cp.async.wait_group 1;" ::: "memory");
}

// ---------------------------------------------------------------------------
// TN tf32 GEMM: C[M,N] = A[M,K] @ B[N,K]^T (+ bias). A,B already tf32-rounded.
// CTA 128x128x32, 128 threads (4 warps = 2M x 2N, warp tile 64x64), 2 CTA/SM.
// 3-stage cp.async pipeline, TK=32 (4 k-steps = 128 warp-MMAs per barrier
// epoch), register-alternating fragment buffers throughout.
// ROWP=36 ≡ 4 (mod 32): cp.async write phases and LDSM row fetches cover
// all 32 banks (same congruence class as the proven ROWP=20 layout).
// ---------------------------------------------------------------------------
#define TM 128
#define TN 128
#define TK 32
#define ROWP 36
#define TILE_BYTES (128 * ROWP * 4)           // 18432 B per operand tile
#define NSTAGE 3
#define SMEM_BYTES (NSTAGE * 2 * TILE_BYTES)  // 110592 B (x2 CTAs = 221 KB/SM)

extern __shared__ uint32_t smu[];

__device__ __forceinline__ void load_frags(uint32_t aBuf, uint32_t bBuf, uint32_t kOff,
                                           uint32_t aLane, uint32_t bLane,
                                           uint32_t af[4][4], uint32_t bf[8][2])
{
    #pragma unroll
    for (int mb = 0; mb < 4; mb++)
        ldsm4(af[mb][0], af[mb][1], af[mb][2], af[mb][3],
              aBuf + aLane + kOff + (uint32_t)(mb * 16 * ROWP * 4));
    #pragma unroll
    for (int q = 0; q < 4; q++)
        ldsm4(bf[2 * q][0], bf[2 * q][1], bf[2 * q + 1][0], bf[2 * q + 1][1],
              bBuf + bLane + kOff + (uint32_t)(q * 16 * ROWP * 4));
}

__device__ __forceinline__ void do_mmas(float acc[4][8][4],
                                        uint32_t af[4][4], uint32_t bf[8][2])
{
    #pragma unroll
    for (int mb = 0; mb < 4; mb++)
        #pragma unroll
        for (int nb = 0; nb < 8; nb++)
            mma16n8k8(acc[mb][nb], af[mb][0], af[mb][1], af[mb][2], af[mb][3],
                      bf[nb][0], bf[nb][1]);
}

__global__ __launch_bounds__(128, 2)
void gemm_tf32mma(const float* __restrict__ A, int lda, long long sA,
                  const float* __restrict__ B, int ldb, long long sB,
                  float* __restrict__ C, int ldc, long long sC,
                  int K, const float* __restrict__ bias, int roundC)
{
    const int tid = threadIdx.x;
    const int wid = tid >> 5, lid = tid & 31;
    const int g = lid >> 2, tq = lid & 3;
    const int wm = wid & 1, wn = wid >> 1;     // warps: 2(M) x 2(N)
    const int bx = blockIdx.x, by = blockIdx.y, bz = blockIdx.z;

    A += (long long)bz * sA + (long long)(by * TM) * lda;
    B += (long long)bz * sB + (long long)(bx * TN) * ldb;
    C += (long long)bz * sC + (long long)(by * TM) * ldc + bx * TN;

    const uint32_t sbase = smem_u32(smu);

    // Copy map: 1 thread per row, 32 floats (8 x cp.async 16B) per operand
    const float* Ap = A + (long long)tid * lda;
    const float* Bp = B + (long long)tid * ldb;
    const uint32_t sts_off = (uint32_t)(tid * ROWP) * 4u;

    // ldmatrix lane addressing (byte offsets within a tile)
    const int laneRowA = lid & 15;
    const int laneColA = (lid >> 4) << 2;
    const uint32_t aLane = (uint32_t)(((wm * 64 + laneRowA) * ROWP + laneColA) * 4);
    const int laneRowB = (lid & 7) | ((lid >> 4) << 3);
    const int laneColB = ((lid >> 3) & 1) << 2;
    const uint32_t bLane = (uint32_t)(((wn * 64 + laneRowB) * ROWP + laneColB) * 4);

    float acc[4][8][4];
    #pragma unroll
    for (int i = 0; i < 4; i++)
        #pragma unroll
        for (int j = 0; j < 8; j++)
            #pragma unroll
            for (int r = 0; r < 4; r++) acc[i][j][r] = 0.f;

    const int NK = K / TK;

    auto stage_copy = [&](int t) {
        const uint32_t dst = sbase + (uint32_t)(t % NSTAGE) * 2 * TILE_BYTES;
        const float* As = Ap + t * TK;
        const float* Bs = Bp + t * TK;
        #pragma unroll
        for (int i = 0; i < 8; i++) cpasync16(dst + sts_off + i * 16, As + i * 4);
        #pragma unroll
        for (int i = 0; i < 8; i++) cpasync16(dst + TILE_BYTES + sts_off + i * 16, Bs + i * 4);
    };

    // ---- prologue: fill 2 stages ----
    stage_copy(0); cp_commit();
    stage_copy(1); cp_commit();
    cp_wait1();                    // stage 0 resident
    __syncthreads();

    // Register-alternating fragments
    uint32_t af[2][4][4], bf[2][8][2];
    load_frags(sbase, sbase + TILE_BYTES, 0, aLane, bLane, af[0], bf[0]);

    for (int t = 0; t < NK; ++t) {
        if (t + 2 < NK) stage_copy(t + 2);
        cp_commit();

        const uint32_t aBuf = sbase + (uint32_t)(t % NSTAGE) * 2 * TILE_BYTES;
        const uint32_t bBuf = aBuf + TILE_BYTES;

        // 4 k-steps per stage; frags for ks+1 load ahead of ks's MMAs
        load_frags(aBuf, bBuf, 1 * 32, aLane, bLane, af[1], bf[1]);
        do_mmas(acc, af[0], bf[0]);                       // ks0
        load_frags(aBuf, bBuf, 2 * 32, aLane, bLane, af[0], bf[0]);
        do_mmas(acc, af[1], bf[1]);                       // ks1
        load_frags(aBuf, bBuf, 3 * 32, aLane, bLane, af[1], bf[1]);
        do_mmas(acc, af[0], bf[0]);                       // ks2

        cp_wait1();               // stage t+1 resident; stage t-1 reads all done
        __syncthreads();

        if (t + 1 < NK) {
            const uint32_t aN = sbase + (uint32_t)((t + 1) % NSTAGE) * 2 * TILE_BYTES;
            load_frags(aN, aN + TILE_BYTES, 0, aLane, bLane, af[0], bf[0]);
        }
        do_mmas(acc, af[1], bf[1]);                       // ks3
    }

    // ---- epilogue ----
    float badd[8][2];
    #pragma unroll
    for (int nb = 0; nb < 8; nb++) {
        const int col = wn * 64 + nb * 8 + tq * 2;
        badd[nb][0] = bias ? __ldg(bias + bx * TN + col)     : 0.f;
        badd[nb][1] = bias ? __ldg(bias + bx * TN + col + 1) : 0.f;
    }
    #pragma unroll
    for (int mb = 0; mb < 4; mb++) {
        const int row = wm * 64 + mb * 16 + g;
        #pragma unroll
        for (int nb = 0; nb < 8; nb++) {
            const int col = wn * 64 + nb * 8 + tq * 2;
            float o0 = acc[mb][nb][0] + badd[nb][0];
            float o1 = acc[mb][nb][1] + badd[nb][1];
            float o2 = acc[mb][nb][2] + badd[nb][0];
            float o3 = acc[mb][nb][3] + badd[nb][1];
            if (roundC) { o0 = roundtf(o0); o1 = roundtf(o1); o2 = roundtf(o2); o3 = roundtf(o3); }
            *(float2*)(C + (long long)row * ldc + col)       = make_float2(o0, o1);
            *(float2*)(C + (long long)(row + 8) * ldc + col) = make_float2(o2, o3);
        }
    }
}

// ---------------------------------------------------------------------------
// Elementwise round-to-tf32 (for x). Grid-stride float4.
// ---------------------------------------------------------------------------
__global__ void round_tf32_kernel(const float* __restrict__ in, float* __restrict__ out,
                                  size_t n4)
{
    size_t i = (size_t)blockIdx.x * blockDim.x + threadIdx.x;
    size_t stride = (size_t)gridDim.x * blockDim.x;
    for (; i < n4; i += stride) {
        float4 v = ((const float4*)in)[i];
        v.x = roundtf(v.x); v.y = roundtf(v.y); v.z = roundtf(v.z); v.w = roundtf(v.w);
        ((float4*)out)[i] = v;
    }
}

// ---------------------------------------------------------------------------
// Generic 32x32 tiled transpose (tf32-rounds its output), batched.
// ---------------------------------------------------------------------------
__global__ void transpose_f32(const float* __restrict__ in, long long sIn, int ldin,
                              float* __restrict__ out, long long sOut, int ldout)
{
    __shared__ float tile[32][33];
    const int b  = blockIdx.z;
    const int c0 = blockIdx.x << 5;
    const int r0 = blockIdx.y << 5;
    const int x = threadIdx.x, y = threadIdx.y;     // 32 x 8
    const float* ip = in + (long long)b * sIn;
    float* op = out + (long long)b * sOut;
    #pragma unroll
    for (int j = 0; j < 32; j += 8)
        tile[y + j][x] = ip[(long long)(r0 + y + j) * ldin + c0 + x];
    __syncthreads();
    #pragma unroll
    for (int j = 0; j < 32; j += 8)
        op[(long long)(c0 + y + j) * ldout + r0 + x] = roundtf(tile[x][y + j]);
}

// ---------------------------------------------------------------------------
// Row softmax over 4096 columns; writes tf32-rounded probabilities.
// ---------------------------------------------------------------------------
__device__ __forceinline__ float warpMax(float v) {
    #pragma unroll
    for (int o = 16; o > 0; o >>= 1) v = fmaxf(v, __shfl_xor_sync(0xffffffffu, v, o));
    return v;
}
__device__ __forceinline__ float warpSum(float v) {
    #pragma unroll
    for (int o = 16; o > 0; o >>= 1) v += __shfl_xor_sync(0xffffffffu, v, o);
    return v;
}

__global__ __launch_bounds__(256, 4)
void softmax4096(float* __restrict__ s, float scale)
{
    float* p = s + (long long)blockIdx.x * 4096;
    const int t = threadIdx.x;
    const int lane = t & 31, wid = t >> 5;
    __shared__ float red[8];

    float4 v[4];
    #pragma unroll
    for (int i = 0; i < 4; i++) {
        v[i] = *(const float4*)(p + i * 1024 + t * 4);
        v[i].x *= scale; v[i].y *= scale; v[i].z *= scale; v[i].w *= scale;
    }
    float m = v[0].x;
    #pragma unroll
    for (int i = 0; i < 4; i++) {
        m = fmaxf(m, v[i].x); m = fmaxf(m, v[i].y);
        m = fmaxf(m, v[i].z); m = fmaxf(m, v[i].w);
    }
    m = warpMax(m);
    if (lane == 0) red[wid] = m;
    __syncthreads();
    m = red[0];
    #pragma unroll
    for (int j = 1; j < 8; j++) m = fmaxf(m, red[j]);

    float sum = 0.f;
    #pragma unroll
    for (int i = 0; i < 4; i++) {
        v[i].x = expf(v[i].x - m); v[i].y = expf(v[i].y - m);
        v[i].z = expf(v[i].z - m); v[i].w = expf(v[i].w - m);
        sum += v[i].x + v[i].y + v[i].z + v[i].w;
    }
    sum = warpSum(sum);
    __syncthreads();
    if (lane == 0) red[wid] = sum;
    __syncthreads();
    float tot = red[0];
    #pragma unroll
    for (int j = 1; j < 8; j++) tot += red[j];
    const float inv = 1.0f / tot;

    #pragma unroll
    for (int i = 0; i < 4; i++) {
        v[i].x = roundtf(v[i].x * inv); v[i].y = roundtf(v[i].y * inv);
        v[i].z = roundtf(v[i].z * inv); v[i].w = roundtf(v[i].w * inv);
        *(float4*)(p + i * 1024 + t * 4) = v[i];
    }
}

// ---------------------------------------------------------------------------
// Launch
// ---------------------------------------------------------------------------
extern "C" void kernel_launch(void* const* d_in, const int* in_sizes, int n_in,
                              void* d_out, int out_size)
{
    (void)in_sizes; (void)n_in; (void)out_size;
    const float* x = (const float*)d_in[0];   // [B,S,D]
    const float* W = (const float*)d_in[1];   // [D,3D]
    const float* b = (const float*)d_in[2];   // [3D]
    float* out = (float*)d_out;               // [B,S,D]

    float *qkv, *wt, *vt, *sc, *xr;
    cudaGetSymbolAddress((void**)&qkv, g_qkv);
    cudaGetSymbolAddress((void**)&wt,  g_wt);
    cudaGetSymbolAddress((void**)&vt,  g_vt);
    cudaGetSymbolAddress((void**)&sc,  g_sc);
    cudaGetSymbolAddress((void**)&xr,  g_xr);

    cudaFuncSetAttribute(gemm_tf32mma, cudaFuncAttributeMaxDynamicSharedMemorySize, SMEM_BYTES);

    // 0a) xr = round_tf32(x)
    round_tf32_kernel<<<1024, 256>>>(x, xr, (size_t)BDIM * SDIM * DDIM / 4);

    // 0b) Wt[e][d] = round_tf32(W[d][e])
    transpose_f32<<<dim3(3 * DDIM / 32, DDIM / 32, 1), dim3(32, 8)>>>(
        W, 0LL, 3 * DDIM, wt, 0LL, DDIM);

    // 1) qkv = round_tf32(xr @ Wt^T + b)   (M=16384, N=3072, K=1024)
    gemm_tf32mma<<<dim3(3 * DDIM / TN, BDIM * SDIM / TM, 1), 128, SMEM_BYTES>>>(
        xr,  DDIM, 0LL,
        wt,  DDIM, 0LL,
        qkv, 3 * DDIM, 0LL,
        DDIM, b, 1);

    // 2) Vt[b][d][s] = V[b][s][d]   (already tf32; transpose re-round is no-op)
    transpose_f32<<<dim3(DDIM / 32, SDIM / 32, BDIM), dim3(32, 8)>>>(
        qkv + 2 * DDIM, (long long)SDIM * 3 * DDIM, 3 * DDIM,
        vt,             (long long)DDIM * SDIM,     SDIM);

    // 3) scores = Q @ K^T   (per batch: M=4096, N=4096, K=1024)
    gemm_tf32mma<<<dim3(SDIM / TN, SDIM / TM, BDIM), 128, SMEM_BYTES>>>(
        qkv,        3 * DDIM, (long long)SDIM * 3 * DDIM,
        qkv + DDIM, 3 * DDIM, (long long)SDIM * 3 * DDIM,
        sc,         SDIM,     (long long)SDIM * SDIM,
        DDIM, (const float*)0, 0);

    // 4) softmax rows (scale = D^-0.5 = 1/32), writes tf32-rounded attn
    softmax4096<<<BDIM * SDIM, 256>>>(sc, 0.03125f);

    // 5) out = P @ Vt^T   (per batch: M=4096, N=1024, K=4096) — NOT rounded
    gemm_tf32mma<<<dim3(DDIM / TN, SDIM / TM, BDIM), 128, SMEM_BYTES>>>(
        sc,  SDIM, (long long)SDIM * SDIM,
        vt,  SDIM, (long long)DDIM * SDIM,
        out, DDIM, (long long)SDIM * DDIM,
        SDIM, (const float*)0, 0);
}

// round 14
// speedup vs baseline: 2.6481x; 1.8720x over previous
#include <cuda_runtime.h>
#include <cuda_fp16.h>
#include <stdint.h>
#include <math.h>

#define BDIM 4
#define SDIM 4096
#define DDIM 1024

// Scratch (device globals — allocation-free per harness rules)
__device__ __half g_xh  [(size_t)BDIM * SDIM * DDIM];      // x  -> fp16
__device__ __half g_wth [(size_t)3 * DDIM * DDIM];         // W^T [3D, D] fp16
__device__ __half g_qkvh[(size_t)BDIM * SDIM * 3 * DDIM];  // qkv [B*S, 3D] fp16
__device__ __half g_vth [(size_t)BDIM * DDIM * SDIM];      // V^T [B][D][S] fp16
__device__ float  g_sc  [(size_t)BDIM * SDIM * SDIM];      // scores f32
__device__ __half g_ph  [(size_t)BDIM * SDIM * SDIM];      // attn probs fp16

// ---------------------------------------------------------------------------
// Arch-portable PTX helpers (NO tcgen05 — harness targets sm_103 base)
// ---------------------------------------------------------------------------
__device__ __forceinline__ uint32_t smem_u32(const void* p) {
    uint32_t a;
    asm("{ .reg .u64 t; cvta.to.shared.u64 t, %1; cvt.u32.u64 %0, t; }" : "=r"(a) : "l"(p));
    return a;
}
__device__ __forceinline__ void mma16n8k16(float c[4],
                                           uint32_t a0, uint32_t a1, uint32_t a2, uint32_t a3,
                                           uint32_t b0, uint32_t b1) {
    asm volatile(
        "mma.sync.aligned.m16n8k16.row.col.f32.f16.f16.f32 "
        "{%0,%1,%2,%3}, {%4,%5,%6,%7}, {%8,%9}, {%0,%1,%2,%3};"
        : "+f"(c[0]), "+f"(c[1]), "+f"(c[2]), "+f"(c[3])
        : "r"(a0), "r"(a1), "r"(a2), "r"(a3), "r"(b0), "r"(b1));
}
__device__ __forceinline__ void ldsm4(uint32_t& r0, uint32_t& r1, uint32_t& r2, uint32_t& r3,
                                      uint32_t addr) {
    asm volatile("ldmatrix.sync.aligned.m8n8.x4.shared.b16 {%0,%1,%2,%3}, [%4];"
                 : "=r"(r0), "=r"(r1), "=r"(r2), "=r"(r3) : "r"(addr));
}
__device__ __forceinline__ void cpasync16(uint32_t s, const void* g) {
    asm volatile("cp.async.cg.shared.global [%0], [%1], 16;" :: "r"(s), "l"(g));
}
__device__ __forceinline__ void cp_commit() {
    asm volatile("cp.async.commit_group;" ::: "memory");
}
__device__ __forceinline__ void cp_wait1() {
    asm volatile("cp.async.wait_group 1;" ::: "memory");
}

// ---------------------------------------------------------------------------
// TN fp16 GEMM (fp32 accum): C[M,N] = A[M,K] @ B[N,K]^T (+ bias).
// CTA 128x128x64, 128 threads (4 warps = 2M x 2N, warp tile 64x64), 2 CTA/SM.
// 3-stage cp.async pipeline; 4 k-steps of k=16 per stage; register-
// alternating fragments. ROWP=72 halves (144 B stride) — byte-identical
// bank behavior to the proven tf32 layout (r*144 mod 128 covers 8 groups).
// ---------------------------------------------------------------------------
#define TM 128
#define TN 128
#define TKH 64                                 // K halves per stage
#define ROWP 72                                // padded row length (halves)
#define TILE_BYTES (128 * ROWP * 2)            // 18432 B per operand tile
#define NSTAGE 3
#define SMEM_BYTES (NSTAGE * 2 * TILE_BYTES)   // 110592 B (x2 CTAs = 221 KB/SM)

extern __shared__ uint32_t smu[];

__device__ __forceinline__ void load_frags(uint32_t aBuf, uint32_t bBuf, uint32_t kOff,
                                           uint32_t aLane, uint32_t bLane,
                                           uint32_t af[4][4], uint32_t bf[8][2])
{
    #pragma unroll
    for (int mb = 0; mb < 4; mb++)
        ldsm4(af[mb][0], af[mb][1], af[mb][2], af[mb][3],
              aBuf + aLane + kOff + (uint32_t)(mb * 16 * ROWP * 2));
    #pragma unroll
    for (int q = 0; q < 4; q++)
        ldsm4(bf[2 * q][0], bf[2 * q][1], bf[2 * q + 1][0], bf[2 * q + 1][1],
              bBuf + bLane + kOff + (uint32_t)(q * 16 * ROWP * 2));
}

__device__ __forceinline__ void do_mmas(float acc[4][8][4],
                                        uint32_t af[4][4], uint32_t bf[8][2])
{
    #pragma unroll
    for (int mb = 0; mb < 4; mb++)
        #pragma unroll
        for (int nb = 0; nb < 8; nb++)
            mma16n8k16(acc[mb][nb], af[mb][0], af[mb][1], af[mb][2], af[mb][3],
                       bf[nb][0], bf[nb][1]);
}

__global__ __launch_bounds__(128, 2)
void gemm_f16mma(const __half* __restrict__ A, int lda, long long sA,
                 const __half* __restrict__ B, int ldb, long long sB,
                 void* __restrict__ Cv, int ldc, long long sC,
                 int K, const float* __restrict__ bias, int halfOut)
{
    const int tid = threadIdx.x;
    const int wid = tid >> 5, lid = tid & 31;
    const int g = lid >> 2, tq = lid & 3;
    const int wm = wid & 1, wn = wid >> 1;     // warps: 2(M) x 2(N)
    const int bx = blockIdx.x, by = blockIdx.y, bz = blockIdx.z;

    A += (long long)bz * sA + (long long)(by * TM) * lda;
    B += (long long)bz * sB + (long long)(bx * TN) * ldb;

    const uint32_t sbase = smem_u32(smu);

    // Copy map: 1 thread per row, 64 halves (8 x cp.async 16B) per operand
    const __half* Ap = A + (long long)tid * lda;
    const __half* Bp = B + (long long)tid * ldb;
    const uint32_t sts_off = (uint32_t)(tid * ROWP) * 2u;

    // ldmatrix lane addressing (byte offsets within a tile)
    //  A (m16k16): lanes 0-15 rows m0-15 @khalf0, 16-31 rows m0-15 @khalf1
    const int laneRowA = lid & 15;
    const uint32_t aLane = (uint32_t)((wm * 64 + laneRowA) * ROWP * 2) + ((lid >> 4) << 4);
    //  B (two n8k16): 0-7 n0-7 kh0, 8-15 n0-7 kh1, 16-23 n8-15 kh0, 24-31 n8-15 kh1
    const int laneRowB = (lid & 7) | ((lid >> 4) << 3);
    const uint32_t bLane = (uint32_t)((wn * 64 + laneRowB) * ROWP * 2) + (((lid >> 3) & 1) << 4);

    float acc[4][8][4];
    #pragma unroll
    for (int i = 0; i < 4; i++)
        #pragma unroll
        for (int j = 0; j < 8; j++)
            #pragma unroll
            for (int r = 0; r < 4; r++) acc[i][j][r] = 0.f;

    const int NK = K / TKH;

    auto stage_copy = [&](int t) {
        const uint32_t dst = sbase + (uint32_t)(t % NSTAGE) * 2 * TILE_BYTES;
        const __half* As = Ap + t * TKH;
        const __half* Bs = Bp + t * TKH;
        #pragma unroll
        for (int i = 0; i < 8; i++) cpasync16(dst + sts_off + i * 16, As + i * 8);
        #pragma unroll
        for (int i = 0; i < 8; i++) cpasync16(dst + TILE_BYTES + sts_off + i * 16, Bs + i * 8);
    };

    // ---- prologue: fill 2 stages ----
    stage_copy(0); cp_commit();
    stage_copy(1); cp_commit();
    cp_wait1();
    __syncthreads();

    // Register-alternating fragments
    uint32_t af[2][4][4], bf[2][8][2];
    load_frags(sbase, sbase + TILE_BYTES, 0, aLane, bLane, af[0], bf[0]);

    for (int t = 0; t < NK; ++t) {
        if (t + 2 < NK) stage_copy(t + 2);
        cp_commit();

        const uint32_t aBuf = sbase + (uint32_t)(t % NSTAGE) * 2 * TILE_BYTES;
        const uint32_t bBuf = aBuf + TILE_BYTES;

        // 4 k-steps (k=16 each) per stage; frags for ks+1 load ahead of ks's MMAs
        load_frags(aBuf, bBuf, 1 * 32, aLane, bLane, af[1], bf[1]);
        do_mmas(acc, af[0], bf[0]);                       // ks0
        load_frags(aBuf, bBuf, 2 * 32, aLane, bLane, af[0], bf[0]);
        do_mmas(acc, af[1], bf[1]);                       // ks1
        load_frags(aBuf, bBuf, 3 * 32, aLane, bLane, af[1], bf[1]);
        do_mmas(acc, af[0], bf[0]);                       // ks2

        cp_wait1();
        __syncthreads();

        if (t + 1 < NK) {
            const uint32_t aN = sbase + (uint32_t)((t + 1) % NSTAGE) * 2 * TILE_BYTES;
            load_frags(aN, aN + TILE_BYTES, 0, aLane, bLane, af[0], bf[0]);
        }
        do_mmas(acc, af[1], bf[1]);                       // ks3
    }

    // ---- epilogue ----
    float badd[8][2];
    #pragma unroll
    for (int nb = 0; nb < 8; nb++) {
        const int col = wn * 64 + nb * 8 + tq * 2;
        badd[nb][0] = bias ? __ldg(bias + bx * TN + col)     : 0.f;
        badd[nb][1] = bias ? __ldg(bias + bx * TN + col + 1) : 0.f;
    }
    if (halfOut) {
        __half* C = (__half*)Cv + (long long)bz * sC + (long long)(by * TM) * ldc + bx * TN;
        #pragma unroll
        for (int mb = 0; mb < 4; mb++) {
            const int row = wm * 64 + mb * 16 + g;
            #pragma unroll
            for (int nb = 0; nb < 8; nb++) {
                const int col = wn * 64 + nb * 8 + tq * 2;
                __half2 v0 = __floats2half2_rn(acc[mb][nb][0] + badd[nb][0],
                                               acc[mb][nb][1] + badd[nb][1]);
                __half2 v1 = __floats2half2_rn(acc[mb][nb][2] + badd[nb][0],
                                               acc[mb][nb][3] + badd[nb][1]);
                *(__half2*)(C + (long long)row * ldc + col)       = v0;
                *(__half2*)(C + (long long)(row + 8) * ldc + col) = v1;
            }
        }
    } else {
        float* C = (float*)Cv + (long long)bz * sC + (long long)(by * TM) * ldc + bx * TN;
        #pragma unroll
        for (int mb = 0; mb < 4; mb++) {
            const int row = wm * 64 + mb * 16 + g;
            #pragma unroll
            for (int nb = 0; nb < 8; nb++) {
                const int col = wn * 64 + nb * 8 + tq * 2;
                *(float2*)(C + (long long)row * ldc + col) =
                    make_float2(acc[mb][nb][0] + badd[nb][0], acc[mb][nb][1] + badd[nb][1]);
                *(float2*)(C + (long long)(row + 8) * ldc + col) =
                    make_float2(acc[mb][nb][2] + badd[nb][0], acc[mb][nb][3] + badd[nb][1]);
            }
        }
    }
}

// ---------------------------------------------------------------------------
// Elementwise f32 -> fp16 (for x). Grid-stride float4 -> 2x half2.
// ---------------------------------------------------------------------------
__global__ void f32_to_h_kernel(const float* __restrict__ in, __half* __restrict__ out,
                                size_t n4)
{
    size_t i = (size_t)blockIdx.x * blockDim.x + threadIdx.x;
    size_t stride = (size_t)gridDim.x * blockDim.x;
    for (; i < n4; i += stride) {
        float4 v = ((const float4*)in)[i];
        __half2* o = (__half2*)(out + i * 4);
        o[0] = __floats2half2_rn(v.x, v.y);
        o[1] = __floats2half2_rn(v.z, v.w);
    }
}

// ---------------------------------------------------------------------------
// Transpose f32 -> fp16: out[c][r] = h(in[r][c]).  (for W^T)
// ---------------------------------------------------------------------------
__global__ void transpose_f2h(const float* __restrict__ in, int ldin,
                              __half* __restrict__ out, int ldout)
{
    __shared__ float tile[32][33];
    const int c0 = blockIdx.x << 5;
    const int r0 = blockIdx.y << 5;
    const int x = threadIdx.x, y = threadIdx.y;     // 32 x 8
    #pragma unroll
    for (int j = 0; j < 32; j += 8)
        tile[y + j][x] = in[(long long)(r0 + y + j) * ldin + c0 + x];
    __syncthreads();
    #pragma unroll
    for (int j = 0; j < 32; j += 8)
        out[(long long)(c0 + y + j) * ldout + r0 + x] = __float2half_rn(tile[x][y + j]);
}

// ---------------------------------------------------------------------------
// Transpose fp16 -> fp16: out[c][r] = in[r][c], batched.  (for V^T)
// ---------------------------------------------------------------------------
__global__ void transpose_h2h(const __half* __restrict__ in, long long sIn, int ldin,
                              __half* __restrict__ out, long long sOut, int ldout)
{
    __shared__ __half tile[32][40];
    const int b  = blockIdx.z;
    const int c0 = blockIdx.x << 5;
    const int r0 = blockIdx.y << 5;
    const int x = threadIdx.x, y = threadIdx.y;     // 32 x 8
    const __half* ip = in + (long long)b * sIn;
    __half* op = out + (long long)b * sOut;
    #pragma unroll
    for (int j = 0; j < 32; j += 8)
        tile[y + j][x] = ip[(long long)(r0 + y + j) * ldin + c0 + x];
    __syncthreads();
    #pragma unroll
    for (int j = 0; j < 32; j += 8)
        op[(long long)(c0 + y + j) * ldout + r0 + x] = tile[x][y + j];
}

// ---------------------------------------------------------------------------
// Row softmax over 4096 f32 scores; writes fp16 probabilities.
// ---------------------------------------------------------------------------
__device__ __forceinline__ float warpMax(float v) {
    #pragma unroll
    for (int o = 16; o > 0; o >>= 1) v = fmaxf(v, __shfl_xor_sync(0xffffffffu, v, o));
    return v;
}
__device__ __forceinline__ float warpSum(float v) {
    #pragma unroll
    for (int o = 16; o > 0; o >>= 1) v += __shfl_xor_sync(0xffffffffu, v, o);
    return v;
}

__global__ __launch_bounds__(256, 4)
void softmax4096(const float* __restrict__ s, __half* __restrict__ pOut, float scale)
{
    const float* p = s + (long long)blockIdx.x * 4096;
    __half* po = pOut + (long long)blockIdx.x * 4096;
    const int t = threadIdx.x;
    const int lane = t & 31, wid = t >> 5;
    __shared__ float red[8];

    float4 v[4];
    #pragma unroll
    for (int i = 0; i < 4; i++) {
        v[i] = *(const float4*)(p + i * 1024 + t * 4);
        v[i].x *= scale; v[i].y *= scale; v[i].z *= scale; v[i].w *= scale;
    }
    float m = v[0].x;
    #pragma unroll
    for (int i = 0; i < 4; i++) {
        m = fmaxf(m, v[i].x); m = fmaxf(m, v[i].y);
        m = fmaxf(m, v[i].z); m = fmaxf(m, v[i].w);
    }
    m = warpMax(m);
    if (lane == 0) red[wid] = m;
    __syncthreads();
    m = red[0];
    #pragma unroll
    for (int j = 1; j < 8; j++) m = fmaxf(m, red[j]);

    float sum = 0.f;
    #pragma unroll
    for (int i = 0; i < 4; i++) {
        v[i].x = expf(v[i].x - m); v[i].y = expf(v[i].y - m);
        v[i].z = expf(v[i].z - m); v[i].w = expf(v[i].w - m);
        sum += v[i].x + v[i].y + v[i].z + v[i].w;
    }
    sum = warpSum(sum);
    __syncthreads();
    if (lane == 0) red[wid] = sum;
    __syncthreads();
    float tot = red[0];
    #pragma unroll
    for (int j = 1; j < 8; j++) tot += red[j];
    const float inv = 1.0f / tot;

    #pragma unroll
    for (int i = 0; i < 4; i++) {
        __half2* o = (__half2*)(po + i * 1024 + t * 4);
        o[0] = __floats2half2_rn(v[i].x * inv, v[i].y * inv);
        o[1] = __floats2half2_rn(v[i].z * inv, v[i].w * inv);
    }
}

// ---------------------------------------------------------------------------
// Launch
// ---------------------------------------------------------------------------
extern "C" void kernel_launch(void* const* d_in, const int* in_sizes, int n_in,
                              void* d_out, int out_size)
{
    (void)in_sizes; (void)n_in; (void)out_size;
    const float* x = (const float*)d_in[0];   // [B,S,D]
    const float* W = (const float*)d_in[1];   // [D,3D]
    const float* b = (const float*)d_in[2];   // [3D]
    float* out = (float*)d_out;               // [B,S,D]

    __half *xh, *wth, *qkvh, *vth, *ph;
    float *sc;
    cudaGetSymbolAddress((void**)&xh,   g_xh);
    cudaGetSymbolAddress((void**)&wth,  g_wth);
    cudaGetSymbolAddress((void**)&qkvh, g_qkvh);
    cudaGetSymbolAddress((void**)&vth,  g_vth);
    cudaGetSymbolAddress((void**)&sc,   g_sc);
    cudaGetSymbolAddress((void**)&ph,   g_ph);

    cudaFuncSetAttribute(gemm_f16mma, cudaFuncAttributeMaxDynamicSharedMemorySize, SMEM_BYTES);

    // 0a) xh = fp16(x)
    f32_to_h_kernel<<<1024, 256>>>(x, xh, (size_t)BDIM * SDIM * DDIM / 4);

    // 0b) Wth[e][d] = fp16(W[d][e])
    transpose_f2h<<<dim3(3 * DDIM / 32, DDIM / 32, 1), dim3(32, 8)>>>(
        W, 3 * DDIM, wth, DDIM);

    // 1) qkvh = fp16(xh @ Wth^T + b)   (M=16384, N=3072, K=1024)
    gemm_f16mma<<<dim3(3 * DDIM / TN, BDIM * SDIM / TM, 1), 128, SMEM_BYTES>>>(
        xh,   DDIM, 0LL,
        wth,  DDIM, 0LL,
        qkvh, 3 * DDIM, 0LL,
        DDIM, b, 1);

    // 2) Vth[b][d][s] = V[b][s][d]
    transpose_h2h<<<dim3(DDIM / 32, SDIM / 32, BDIM), dim3(32, 8)>>>(
        qkvh + 2 * DDIM, (long long)SDIM * 3 * DDIM, 3 * DDIM,
        vth,             (long long)DDIM * SDIM,     SDIM);

    // 3) scores = Q @ K^T   (per batch: M=4096, N=4096, K=1024), f32 out
    gemm_f16mma<<<dim3(SDIM / TN, SDIM / TM, BDIM), 128, SMEM_BYTES>>>(
        qkvh,        3 * DDIM, (long long)SDIM * 3 * DDIM,
        qkvh + DDIM, 3 * DDIM, (long long)SDIM * 3 * DDIM,
        sc,          SDIM,     (long long)SDIM * SDIM,
        DDIM, (const float*)0, 0);

    // 4) softmax rows (scale = 1/32): f32 scores -> fp16 probs
    softmax4096<<<BDIM * SDIM, 256>>>(sc, ph, 0.03125f);

    // 5) out = P @ Vth^T   (per batch: M=4096, N=1024, K=4096), f32 out
    gemm_f16mma<<<dim3(DDIM / TN, SDIM / TM, BDIM), 128, SMEM_BYTES>>>(
        ph,  SDIM, (long long)SDIM * SDIM,
        vth, SDIM, (long long)DDIM * SDIM,
        out, DDIM, (long long)SDIM * DDIM,
        SDIM, (const float*)0, 0);
}

// round 15
// speedup vs baseline: 2.7740x; 1.0475x over previous
#include <cuda_runtime.h>
#include <cuda_fp16.h>
#include <stdint.h>
#include <math.h>

#define BDIM 4
#define SDIM 4096
#define DDIM 1024

// Scratch (device globals — allocation-free per harness rules)
__device__ __half g_xh  [(size_t)BDIM * SDIM * DDIM];      // x  -> fp16
__device__ __half g_wth [(size_t)3 * DDIM * DDIM];         // W^T [3D, D] fp16
__device__ __half g_qkvh[(size_t)BDIM * SDIM * 3 * DDIM];  // qkv [B*S, 3D] fp16
__device__ float  g_sc  [(size_t)BDIM * SDIM * SDIM];      // scaled scores f32
__device__ __half g_ph  [(size_t)BDIM * SDIM * SDIM];      // attn probs fp16

// ---------------------------------------------------------------------------
// Arch-portable PTX helpers (NO tcgen05 — harness targets sm_103 base)
// ---------------------------------------------------------------------------
__device__ __forceinline__ uint32_t smem_u32(const void* p) {
    uint32_t a;
    asm("{ .reg .u64 t; cvta.to.shared.u64 t, %1; cvt.u32.u64 %0, t; }" : "=r"(a) : "l"(p));
    return a;
}
__device__ __forceinline__ void mma16n8k16(float c[4],
                                           uint32_t a0, uint32_t a1, uint32_t a2, uint32_t a3,
                                           uint32_t b0, uint32_t b1) {
    asm volatile(
        "mma.sync.aligned.m16n8k16.row.col.f32.f16.f16.f32 "
        "{%0,%1,%2,%3}, {%4,%5,%6,%7}, {%8,%9}, {%0,%1,%2,%3};"
        : "+f"(c[0]), "+f"(c[1]), "+f"(c[2]), "+f"(c[3])
        : "r"(a0), "r"(a1), "r"(a2), "r"(a3), "r"(b0), "r"(b1));
}
__device__ __forceinline__ void ldsm4(uint32_t& r0, uint32_t& r1, uint32_t& r2, uint32_t& r3,
                                      uint32_t addr) {
    asm volatile("ldmatrix.sync.aligned.m8n8.x4.shared.b16 {%0,%1,%2,%3}, [%4];"
                 : "=r"(r0), "=r"(r1), "=r"(r2), "=r"(r3) : "r"(addr));
}
__device__ __forceinline__ void ldsm4t(uint32_t& r0, uint32_t& r1, uint32_t& r2, uint32_t& r3,
                                       uint32_t addr) {
    asm volatile("ldmatrix.sync.aligned.m8n8.x4.trans.shared.b16 {%0,%1,%2,%3}, [%4];"
                 : "=r"(r0), "=r"(r1), "=r"(r2), "=r"(r3) : "r"(addr));
}
__device__ __forceinline__ void cpasync16(uint32_t s, const void* g) {
    asm volatile("cp.async.cg.shared.global [%0], [%1], 16;" :: "r"(s), "l"(g));
}
__device__ __forceinline__ void cp_commit() {
    asm volatile("cp.async.commit_group;" ::: "memory");
}
__device__ __forceinline__ void cp_wait1() {
    asm volatile("cp.async.wait_group 1;" ::: "memory");
}

// ---------------------------------------------------------------------------
// TN fp16 GEMM (fp32 accum), templated on B layout:
//   TRANSB=0: B[N,K] row-major (K-major rows)     — QKV / scores
//   TRANSB=1: B[K,N] row-major (natural V layout) — PV, via ldmatrix.trans
// CTA 128x128x64, 128 threads (4 warps = 2M x 2N, warp tile 64x64), 2 CTA/SM.
// 3-stage cp.async pipeline; 4 k-steps of k=16; register-alternating frags.
// A tile: 128 x ROWP halves (144B rows). B tile (trans): 64 x ROWPB (272B rows);
// ldsm.trans phase = 17*r mod 8 -> conflict-free.
// ---------------------------------------------------------------------------
#define TM 128
#define TN 128
#define TKH 64
#define ROWP 72
#define ROWPB 136
#define A_TILE (128 * ROWP * 2)                  // 18432 B
#define B_TILE_N (128 * ROWP * 2)                // 18432 B  (TRANSB=0)
#define B_TILE_T (64 * ROWPB * 2)                // 17408 B  (TRANSB=1)
#define NSTAGE 3
#define SMEM_MAX (NSTAGE * (A_TILE + B_TILE_N))  // 110592 B

extern __shared__ uint32_t smu[];

template<int TRANSB>
__device__ __forceinline__ void load_frags(uint32_t aBuf, uint32_t bBuf, int ks,
                                           uint32_t aLane, uint32_t bLane,
                                           uint32_t af[4][4], uint32_t bf[8][2])
{
    const uint32_t aOff = (uint32_t)(ks * 32);
    #pragma unroll
    for (int mb = 0; mb < 4; mb++)
        ldsm4(af[mb][0], af[mb][1], af[mb][2], af[mb][3],
              aBuf + aLane + aOff + (uint32_t)(mb * 16 * ROWP * 2));
    if (TRANSB) {
        const uint32_t bOff = (uint32_t)(ks * 16 * ROWPB * 2);
        #pragma unroll
        for (int q = 0; q < 4; q++)
            ldsm4t(bf[2 * q][0], bf[2 * q][1], bf[2 * q + 1][0], bf[2 * q + 1][1],
                   bBuf + bLane + bOff + (uint32_t)(q * 32));
    } else {
        const uint32_t bOff = (uint32_t)(ks * 32);
        #pragma unroll
        for (int q = 0; q < 4; q++)
            ldsm4(bf[2 * q][0], bf[2 * q][1], bf[2 * q + 1][0], bf[2 * q + 1][1],
                  bBuf + bLane + bOff + (uint32_t)(q * 16 * ROWP * 2));
    }
}

__device__ __forceinline__ void do_mmas(float acc[4][8][4],
                                        uint32_t af[4][4], uint32_t bf[8][2])
{
    #pragma unroll
    for (int mb = 0; mb < 4; mb++)
        #pragma unroll
        for (int nb = 0; nb < 8; nb++)
            mma16n8k16(acc[mb][nb], af[mb][0], af[mb][1], af[mb][2], af[mb][3],
                       bf[nb][0], bf[nb][1]);
}

template<int TRANSB>
__global__ __launch_bounds__(128, 2)
void gemm_f16mma(const __half* __restrict__ A, int lda, long long sA,
                 const __half* __restrict__ B, int ldb, long long sB,
                 void* __restrict__ Cv, int ldc, long long sC,
                 int K, const float* __restrict__ bias, float cmul, int halfOut)
{
    const int tid = threadIdx.x;
    const int wid = tid >> 5, lid = tid & 31;
    const int g = lid >> 2, tq = lid & 3;
    const int wm = wid & 1, wn = wid >> 1;     // warps: 2(M) x 2(N)
    const int bx = blockIdx.x, by = blockIdx.y, bz = blockIdx.z;

    const int B_TILE = TRANSB ? B_TILE_T : B_TILE_N;
    const int STAGE_B = A_TILE + B_TILE;

    A += (long long)bz * sA + (long long)(by * TM) * lda;
    if (TRANSB) B += (long long)bz * sB + bx * TN;                      // B[k][n]
    else        B += (long long)bz * sB + (long long)(bx * TN) * ldb;   // B[n][k]

    const uint32_t sbase = smem_u32(smu);

    // A copy map: 1 thread per row, 64 halves (8 x 16B)
    const __half* Ap = A + (long long)tid * lda;
    const uint32_t aSts = (uint32_t)(tid * ROWP) * 2u;
    // B copy map
    const __half* Bp;
    uint32_t bSts;
    if (TRANSB) {   // rows = k (64), 2 threads/row, alternating 16B chunks
        Bp = B + (long long)(tid >> 1) * ldb + (tid & 1) * 8;
        bSts = (uint32_t)((tid >> 1) * ROWPB + (tid & 1) * 8) * 2u;
    } else {        // rows = n (128), 1 thread/row
        Bp = B + (long long)tid * ldb;
        bSts = (uint32_t)(tid * ROWP) * 2u;
    }

    // ldmatrix lane addressing (byte offsets within a tile)
    const int laneRowA = lid & 15;
    const uint32_t aLane = (uint32_t)((wm * 64 + laneRowA) * ROWP * 2) + ((lid >> 4) << 4);
    uint32_t bLane;
    if (TRANSB) {   // kr = (lid&7)|(lid&8); ncol = wn*64 + 8*(lid>>4) (+q*16 per call)
        const int kr = (lid & 7) | (lid & 8);
        bLane = (uint32_t)(kr * ROWPB * 2) + (uint32_t)((wn * 64 + 8 * (lid >> 4)) * 2);
    } else {
        const int laneRowB = (lid & 7) | ((lid >> 4) << 3);
        bLane = (uint32_t)((wn * 64 + laneRowB) * ROWP * 2) + (((lid >> 3) & 1) << 4);
    }

    float acc[4][8][4];
    #pragma unroll
    for (int i = 0; i < 4; i++)
        #pragma unroll
        for (int j = 0; j < 8; j++)
            #pragma unroll
            for (int r = 0; r < 4; r++) acc[i][j][r] = 0.f;

    const int NK = K / TKH;

    auto stage_copy = [&](int t) {
        const uint32_t dst = sbase + (uint32_t)(t % NSTAGE) * STAGE_B;
        const __half* As = Ap + t * TKH;
        #pragma unroll
        for (int i = 0; i < 8; i++) cpasync16(dst + aSts + i * 16, As + i * 8);
        const uint32_t bDst = dst + A_TILE;
        if (TRANSB) {
            const __half* Bs = Bp + (long long)(t * TKH) * ldb;
            #pragma unroll
            for (int i = 0; i < 8; i++) cpasync16(bDst + bSts + i * 32, Bs + i * 16);
        } else {
            const __half* Bs = Bp + t * TKH;
            #pragma unroll
            for (int i = 0; i < 8; i++) cpasync16(bDst + bSts + i * 16, Bs + i * 8);
        }
    };

    // ---- prologue: fill 2 stages ----
    stage_copy(0); cp_commit();
    stage_copy(1); cp_commit();
    cp_wait1();
    __syncthreads();

    // Register-alternating fragments
    uint32_t af[2][4][4], bf[2][8][2];
    load_frags<TRANSB>(sbase, sbase + A_TILE, 0, aLane, bLane, af[0], bf[0]);

    for (int t = 0; t < NK; ++t) {
        if (t + 2 < NK) stage_copy(t + 2);
        cp_commit();

        const uint32_t aBuf = sbase + (uint32_t)(t % NSTAGE) * STAGE_B;
        const uint32_t bBuf = aBuf + A_TILE;

        load_frags<TRANSB>(aBuf, bBuf, 1, aLane, bLane, af[1], bf[1]);
        do_mmas(acc, af[0], bf[0]);                       // ks0
        load_frags<TRANSB>(aBuf, bBuf, 2, aLane, bLane, af[0], bf[0]);
        do_mmas(acc, af[1], bf[1]);                       // ks1
        load_frags<TRANSB>(aBuf, bBuf, 3, aLane, bLane, af[1], bf[1]);
        do_mmas(acc, af[0], bf[0]);                       // ks2

        cp_wait1();
        __syncthreads();

        if (t + 1 < NK) {
            const uint32_t aN = sbase + (uint32_t)((t + 1) % NSTAGE) * STAGE_B;
            load_frags<TRANSB>(aN, aN + A_TILE, 0, aLane, bLane, af[0], bf[0]);
        }
        do_mmas(acc, af[1], bf[1]);                       // ks3
    }

    // ---- epilogue ----
    float badd[8][2];
    #pragma unroll
    for (int nb = 0; nb < 8; nb++) {
        const int col = wn * 64 + nb * 8 + tq * 2;
        badd[nb][0] = bias ? __ldg(bias + bx * TN + col)     : 0.f;
        badd[nb][1] = bias ? __ldg(bias + bx * TN + col + 1) : 0.f;
    }
    if (halfOut) {
        __half* C = (__half*)Cv + (long long)bz * sC + (long long)(by * TM) * ldc + bx * TN;
        #pragma unroll
        for (int mb = 0; mb < 4; mb++) {
            const int row = wm * 64 + mb * 16 + g;
            #pragma unroll
            for (int nb = 0; nb < 8; nb++) {
                const int col = wn * 64 + nb * 8 + tq * 2;
                __half2 v0 = __floats2half2_rn(fmaf(acc[mb][nb][0], cmul, badd[nb][0]),
                                               fmaf(acc[mb][nb][1], cmul, badd[nb][1]));
                __half2 v1 = __floats2half2_rn(fmaf(acc[mb][nb][2], cmul, badd[nb][0]),
                                               fmaf(acc[mb][nb][3], cmul, badd[nb][1]));
                *(__half2*)(C + (long long)row * ldc + col)       = v0;
                *(__half2*)(C + (long long)(row + 8) * ldc + col) = v1;
            }
        }
    } else {
        float* C = (float*)Cv + (long long)bz * sC + (long long)(by * TM) * ldc + bx * TN;
        #pragma unroll
        for (int mb = 0; mb < 4; mb++) {
            const int row = wm * 64 + mb * 16 + g;
            #pragma unroll
            for (int nb = 0; nb < 8; nb++) {
                const int col = wn * 64 + nb * 8 + tq * 2;
                *(float2*)(C + (long long)row * ldc + col) =
                    make_float2(fmaf(acc[mb][nb][0], cmul, badd[nb][0]),
                                fmaf(acc[mb][nb][1], cmul, badd[nb][1]));
                *(float2*)(C + (long long)(row + 8) * ldc + col) =
                    make_float2(fmaf(acc[mb][nb][2], cmul, badd[nb][0]),
                                fmaf(acc[mb][nb][3], cmul, badd[nb][1]));
            }
        }
    }
}

// ---------------------------------------------------------------------------
// Elementwise f32 -> fp16 (for x). Grid-stride float4 -> 2x half2.
// ---------------------------------------------------------------------------
__global__ void f32_to_h_kernel(const float* __restrict__ in, __half* __restrict__ out,
                                size_t n4)
{
    size_t i = (size_t)blockIdx.x * blockDim.x + threadIdx.x;
    size_t stride = (size_t)gridDim.x * blockDim.x;
    for (; i < n4; i += stride) {
        float4 v = ((const float4*)in)[i];
        __half2* o = (__half2*)(out + i * 4);
        o[0] = __floats2half2_rn(v.x, v.y);
        o[1] = __floats2half2_rn(v.z, v.w);
    }
}

// ---------------------------------------------------------------------------
// Transpose f32 -> fp16: out[c][r] = h(in[r][c]).  (for W^T)
// ---------------------------------------------------------------------------
__global__ void transpose_f2h(const float* __restrict__ in, int ldin,
                              __half* __restrict__ out, int ldout)
{
    __shared__ float tile[32][33];
    const int c0 = blockIdx.x << 5;
    const int r0 = blockIdx.y << 5;
    const int x = threadIdx.x, y = threadIdx.y;     // 32 x 8
    #pragma unroll
    for (int j = 0; j < 32; j += 8)
        tile[y + j][x] = in[(long long)(r0 + y + j) * ldin + c0 + x];
    __syncthreads();
    #pragma unroll
    for (int j = 0; j < 32; j += 8)
        out[(long long)(c0 + y + j) * ldout + r0 + x] = __float2half_rn(tile[x][y + j]);
}

// ---------------------------------------------------------------------------
// Row softmax over 4096 pre-scaled f32 scores; writes fp16 probabilities.
// ---------------------------------------------------------------------------
__device__ __forceinline__ float warpMax(float v) {
    #pragma unroll
    for (int o = 16; o > 0; o >>= 1) v = fmaxf(v, __shfl_xor_sync(0xffffffffu, v, o));
    return v;
}
__device__ __forceinline__ float warpSum(float v) {
    #pragma unroll
    for (int o = 16; o > 0; o >>= 1) v += __shfl_xor_sync(0xffffffffu, v, o);
    return v;
}

__global__ __launch_bounds__(256, 4)
void softmax4096(const float* __restrict__ s, __half* __restrict__ pOut)
{
    const float* p = s + (long long)blockIdx.x * 4096;
    __half* po = pOut + (long long)blockIdx.x * 4096;
    const int t = threadIdx.x;
    const int lane = t & 31, wid = t >> 5;
    __shared__ float red[8];

    float4 v[4];
    #pragma unroll
    for (int i = 0; i < 4; i++) v[i] = *(const float4*)(p + i * 1024 + t * 4);

    float m = v[0].x;
    #pragma unroll
    for (int i = 0; i < 4; i++) {
        m = fmaxf(m, v[i].x); m = fmaxf(m, v[i].y);
        m = fmaxf(m, v[i].z); m = fmaxf(m, v[i].w);
    }
    m = warpMax(m);
    if (lane == 0) red[wid] = m;
    __syncthreads();
    m = red[0];
    #pragma unroll
    for (int j = 1; j < 8; j++) m = fmaxf(m, red[j]);

    float sum = 0.f;
    #pragma unroll
    for (int i = 0; i < 4; i++) {
        v[i].x = __expf(v[i].x - m); v[i].y = __expf(v[i].y - m);
        v[i].z = __expf(v[i].z - m); v[i].w = __expf(v[i].w - m);
        sum += v[i].x + v[i].y + v[i].z + v[i].w;
    }
    sum = warpSum(sum);
    __syncthreads();
    if (lane == 0) red[wid] = sum;
    __syncthreads();
    float tot = red[0];
    #pragma unroll
    for (int j = 1; j < 8; j++) tot += red[j];
    const float inv = 1.0f / tot;

    #pragma unroll
    for (int i = 0; i < 4; i++) {
        __half2* o = (__half2*)(po + i * 1024 + t * 4);
        o[0] = __floats2half2_rn(v[i].x * inv, v[i].y * inv);
        o[1] = __floats2half2_rn(v[i].z * inv, v[i].w * inv);
    }
}

// ---------------------------------------------------------------------------
// Launch
// ---------------------------------------------------------------------------
extern "C" void kernel_launch(void* const* d_in, const int* in_sizes, int n_in,
                              void* d_out, int out_size)
{
    (void)in_sizes; (void)n_in; (void)out_size;
    const float* x = (const float*)d_in[0];   // [B,S,D]
    const float* W = (const float*)d_in[1];   // [D,3D]
    const float* b = (const float*)d_in[2];   // [3D]
    float* out = (float*)d_out;               // [B,S,D]

    __half *xh, *wth, *qkvh, *ph;
    float *sc;
    cudaGetSymbolAddress((void**)&xh,   g_xh);
    cudaGetSymbolAddress((void**)&wth,  g_wth);
    cudaGetSymbolAddress((void**)&qkvh, g_qkvh);
    cudaGetSymbolAddress((void**)&sc,   g_sc);
    cudaGetSymbolAddress((void**)&ph,   g_ph);

    cudaFuncSetAttribute(gemm_f16mma<0>, cudaFuncAttributeMaxDynamicSharedMemorySize, SMEM_MAX);
    cudaFuncSetAttribute(gemm_f16mma<1>, cudaFuncAttributeMaxDynamicSharedMemorySize, SMEM_MAX);

    // 0a) xh = fp16(x)
    f32_to_h_kernel<<<1024, 256>>>(x, xh, (size_t)BDIM * SDIM * DDIM / 4);

    // 0b) Wth[e][d] = fp16(W[d][e])
    transpose_f2h<<<dim3(3 * DDIM / 32, DDIM / 32, 1), dim3(32, 8)>>>(
        W, 3 * DDIM, wth, DDIM);

    // 1) qkvh = fp16(xh @ Wth^T + b)   (M=16384, N=3072, K=1024)
    gemm_f16mma<0><<<dim3(3 * DDIM / TN, BDIM * SDIM / TM, 1), 128, SMEM_MAX>>>(
        xh,   DDIM, 0LL,
        wth,  DDIM, 0LL,
        qkvh, 3 * DDIM, 0LL,
        DDIM, b, 1.0f, 1);

    // 2) scores = (Q @ K^T) * 1/32   (per batch: M=4096, N=4096, K=1024), f32
    gemm_f16mma<0><<<dim3(SDIM / TN, SDIM / TM, BDIM), 128, SMEM_MAX>>>(
        qkvh,        3 * DDIM, (long long)SDIM * 3 * DDIM,
        qkvh + DDIM, 3 * DDIM, (long long)SDIM * 3 * DDIM,
        sc,          SDIM,     (long long)SDIM * SDIM,
        DDIM, (const float*)0, 0.03125f, 0);

    // 3) softmax rows: f32 scaled scores -> fp16 probs
    softmax4096<<<BDIM * SDIM, 256>>>(sc, ph);

    // 4) out = P @ V   (per batch: M=4096, N=1024, K=4096), V read in natural
    //    [s][d] layout directly from qkvh via ldmatrix.trans, f32 out
    gemm_f16mma<1><<<dim3(DDIM / TN, SDIM / TM, BDIM), 128, SMEM_MAX>>>(
        ph,              SDIM,     (long long)SDIM * SDIM,
        qkvh + 2 * DDIM, 3 * DDIM, (long long)SDIM * 3 * DDIM,
        out,             DDIM,     (long long)SDIM * DDIM,
        SDIM, (const float*)0, 1.0f, 0);
}

// round 16
// speedup vs baseline: 3.3337x; 1.2018x over previous
#include <cuda_runtime.h>
#include <cuda_fp16.h>
#include <stdint.h>
#include <math.h>

#define BDIM 4
#define SDIM 4096
#define DDIM 1024

// Scratch (device globals — allocation-free per harness rules)
__device__ __half g_xh  [(size_t)BDIM * SDIM * DDIM];      // x  -> fp16
__device__ __half g_wth [(size_t)3 * DDIM * DDIM];         // W^T [3D, D] fp16
__device__ __half g_qkvh[(size_t)BDIM * SDIM * 3 * DDIM];  // qkv [B*S, 3D] fp16
__device__ float  g_sc  [(size_t)BDIM * SDIM * SDIM];      // scaled scores f32
__device__ __half g_ph  [(size_t)BDIM * SDIM * SDIM];      // attn probs fp16

// ---------------------------------------------------------------------------
// Arch-portable PTX helpers (NO tcgen05 — harness targets sm_103 base)
// ---------------------------------------------------------------------------
__device__ __forceinline__ uint32_t smem_u32(const void* p) {
    uint32_t a;
    asm("{ .reg .u64 t; cvta.to.shared.u64 t, %1; cvt.u32.u64 %0, t; }" : "=r"(a) : "l"(p));
    return a;
}
__device__ __forceinline__ void mma16n8k16(float c[4],
                                           uint32_t a0, uint32_t a1, uint32_t a2, uint32_t a3,
                                           uint32_t b0, uint32_t b1) {
    asm volatile(
        "mma.sync.aligned.m16n8k16.row.col.f32.f16.f16.f32 "
        "{%0,%1,%2,%3}, {%4,%5,%6,%7}, {%8,%9}, {%0,%1,%2,%3};"
        : "+f"(c[0]), "+f"(c[1]), "+f"(c[2]), "+f"(c[3])
        : "r"(a0), "r"(a1), "r"(a2), "r"(a3), "r"(b0), "r"(b1));
}
__device__ __forceinline__ void ldsm4(uint32_t& r0, uint32_t& r1, uint32_t& r2, uint32_t& r3,
                                      uint32_t addr) {
    asm volatile("ldmatrix.sync.aligned.m8n8.x4.shared.b16 {%0,%1,%2,%3}, [%4];"
                 : "=r"(r0), "=r"(r1), "=r"(r2), "=r"(r3) : "r"(addr));
}
__device__ __forceinline__ void ldsm4t(uint32_t& r0, uint32_t& r1, uint32_t& r2, uint32_t& r3,
                                       uint32_t addr) {
    asm volatile("ldmatrix.sync.aligned.m8n8.x4.trans.shared.b16 {%0,%1,%2,%3}, [%4];"
                 : "=r"(r0), "=r"(r1), "=r"(r2), "=r"(r3) : "r"(addr));
}
__device__ __forceinline__ void cpasync16(uint32_t s, const void* g) {
    asm volatile("cp.async.cg.shared.global [%0], [%1], 16;" :: "r"(s), "l"(g));
}
__device__ __forceinline__ void cp_commit() {
    asm volatile("cp.async.commit_group;" ::: "memory");
}
__device__ __forceinline__ void cp_wait1() {
    asm volatile("cp.async.wait_group 1;" ::: "memory");
}

// ---------------------------------------------------------------------------
// TN fp16 GEMM (fp32 accum), templated on B layout:
//   TRANSB=0: B[N,K] row-major (K-major rows)     — QKV / scores
//   TRANSB=1: B[K,N] row-major (natural V layout) — PV, via ldmatrix.trans
// CTA 128x256x64, 256 threads (8 warps = 2M x 4N, warp tile 64x64), 1 CTA/SM.
// Wider CTA shares staged operands across more warps: smem traffic drops from
// 256 B/MMA (2x2 warps) to 176 B/MMA -> higher tensor-pipe ceiling.
// 3-stage cp.async pipeline; 4 k-steps of k=16; register-alternating frags.
// ---------------------------------------------------------------------------
#define TM 128
#define TN 256
#define TKH 64
#define ROWP 72                                  // A / B(N-major) row pad, halves
#define ROWPB 264                                // B(trans) row pad, halves (528 B)
#define A_TILE (128 * ROWP * 2)                  // 18432 B
#define B_TILE_N (256 * ROWP * 2)                // 36864 B  (TRANSB=0)
#define B_TILE_T (64 * ROWPB * 2)                // 33792 B  (TRANSB=1)
#define NSTAGE 3
#define SMEM_MAX (NSTAGE * (A_TILE + B_TILE_N))  // 165888 B

extern __shared__ uint32_t smu[];

template<int TRANSB>
__device__ __forceinline__ void load_frags(uint32_t aBuf, uint32_t bBuf, int ks,
                                           uint32_t aLane, uint32_t bLane,
                                           uint32_t af[4][4], uint32_t bf[8][2])
{
    const uint32_t aOff = (uint32_t)(ks * 32);
    #pragma unroll
    for (int mb = 0; mb < 4; mb++)
        ldsm4(af[mb][0], af[mb][1], af[mb][2], af[mb][3],
              aBuf + aLane + aOff + (uint32_t)(mb * 16 * ROWP * 2));
    if (TRANSB) {
        const uint32_t bOff = (uint32_t)(ks * 16 * ROWPB * 2);
        #pragma unroll
        for (int q = 0; q < 4; q++)
            ldsm4t(bf[2 * q][0], bf[2 * q][1], bf[2 * q + 1][0], bf[2 * q + 1][1],
                   bBuf + bLane + bOff + (uint32_t)(q * 32));
    } else {
        const uint32_t bOff = (uint32_t)(ks * 32);
        #pragma unroll
        for (int q = 0; q < 4; q++)
            ldsm4(bf[2 * q][0], bf[2 * q][1], bf[2 * q + 1][0], bf[2 * q + 1][1],
                  bBuf + bLane + bOff + (uint32_t)(q * 16 * ROWP * 2));
    }
}

__device__ __forceinline__ void do_mmas(float acc[4][8][4],
                                        uint32_t af[4][4], uint32_t bf[8][2])
{
    #pragma unroll
    for (int mb = 0; mb < 4; mb++)
        #pragma unroll
        for (int nb = 0; nb < 8; nb++)
            mma16n8k16(acc[mb][nb], af[mb][0], af[mb][1], af[mb][2], af[mb][3],
                       bf[nb][0], bf[nb][1]);
}

template<int TRANSB>
__global__ __launch_bounds__(256, 1)
void gemm_f16mma(const __half* __restrict__ A, int lda, long long sA,
                 const __half* __restrict__ B, int ldb, long long sB,
                 void* __restrict__ Cv, int ldc, long long sC,
                 int K, const float* __restrict__ bias, float cmul, int halfOut)
{
    const int tid = threadIdx.x;
    const int wid = tid >> 5, lid = tid & 31;
    const int g = lid >> 2, tq = lid & 3;
    const int wm = wid & 1, wn = wid >> 1;     // warps: 2(M) x 4(N)
    const int bx = blockIdx.x, by = blockIdx.y, bz = blockIdx.z;

    const int B_TILE = TRANSB ? B_TILE_T : B_TILE_N;
    const int STAGE_B = A_TILE + B_TILE;

    A += (long long)bz * sA + (long long)(by * TM) * lda;
    if (TRANSB) B += (long long)bz * sB + bx * TN;                      // B[k][n]
    else        B += (long long)bz * sB + (long long)(bx * TN) * ldb;   // B[n][k]

    const uint32_t sbase = smem_u32(smu);

    // A copy map: 2 threads per row (128 rows), 32 halves each (4 x 16B)
    const int aRow = tid >> 1;
    const int aKof = (tid & 1) * 32;
    const __half* Ap = A + (long long)aRow * lda + aKof;
    const uint32_t aSts = (uint32_t)(aRow * ROWP + aKof) * 2u;
    // B copy map
    const __half* Bp;
    uint32_t bSts;
    if (TRANSB) {   // 64 rows, 4 threads/row; chunk offsets cg*32 + j*16 + i*128 B
        Bp = B + (long long)(tid >> 2) * ldb;
        bSts = (uint32_t)((tid >> 2) * ROWPB) * 2u;
    } else {        // 256 rows, 1 thread/row, 64 halves (8 x 16B)
        Bp = B + (long long)tid * ldb;
        bSts = (uint32_t)(tid * ROWP) * 2u;
    }
    const uint32_t bCg = (uint32_t)(tid & 3) * 32u;   // TRANSB column-group base (bytes)

    // ldmatrix lane addressing (byte offsets within a tile)
    const int laneRowA = lid & 15;
    const uint32_t aLane = (uint32_t)((wm * 64 + laneRowA) * ROWP * 2) + ((lid >> 4) << 4);
    uint32_t bLane;
    if (TRANSB) {   // kr = (lid&7)|(lid&8); ncol = wn*64 + 8*(lid>>4) (+q*16 per call)
        const int kr = (lid & 7) | (lid & 8);
        bLane = (uint32_t)(kr * ROWPB * 2) + (uint32_t)((wn * 64 + 8 * (lid >> 4)) * 2);
    } else {
        const int laneRowB = (lid & 7) | ((lid >> 4) << 3);
        bLane = (uint32_t)((wn * 64 + laneRowB) * ROWP * 2) + (((lid >> 3) & 1) << 4);
    }

    float acc[4][8][4];
    #pragma unroll
    for (int i = 0; i < 4; i++)
        #pragma unroll
        for (int j = 0; j < 8; j++)
            #pragma unroll
            for (int r = 0; r < 4; r++) acc[i][j][r] = 0.f;

    const int NK = K / TKH;

    auto stage_copy = [&](int t) {
        const uint32_t dst = sbase + (uint32_t)(t % NSTAGE) * STAGE_B;
        const __half* As = Ap + t * TKH;
        #pragma unroll
        for (int i = 0; i < 4; i++) cpasync16(dst + aSts + i * 16, As + i * 8);
        const uint32_t bDst = dst + A_TILE;
        if (TRANSB) {
            const __half* Bs = Bp + (long long)(t * TKH) * ldb;
            #pragma unroll
            for (int i = 0; i < 8; i++) {
                const uint32_t off = bCg + (uint32_t)((i & 1) * 16 + (i >> 1) * 128);
                cpasync16(bDst + bSts + off, (const char*)Bs + off);
            }
        } else {
            const __half* Bs = Bp + t * TKH;
            #pragma unroll
            for (int i = 0; i < 8; i++) cpasync16(bDst + bSts + i * 16, Bs + i * 8);
        }
    };

    // ---- prologue: fill 2 stages ----
    stage_copy(0); cp_commit();
    stage_copy(1); cp_commit();
    cp_wait1();
    __syncthreads();

    // Register-alternating fragments
    uint32_t af[2][4][4], bf[2][8][2];
    load_frags<TRANSB>(sbase, sbase + A_TILE, 0, aLane, bLane, af[0], bf[0]);

    for (int t = 0; t < NK; ++t) {
        if (t + 2 < NK) stage_copy(t + 2);
        cp_commit();

        const uint32_t aBuf = sbase + (uint32_t)(t % NSTAGE) * STAGE_B;
        const uint32_t bBuf = aBuf + A_TILE;

        load_frags<TRANSB>(aBuf, bBuf, 1, aLane, bLane, af[1], bf[1]);
        do_mmas(acc, af[0], bf[0]);                       // ks0
        load_frags<TRANSB>(aBuf, bBuf, 2, aLane, bLane, af[0], bf[0]);
        do_mmas(acc, af[1], bf[1]);                       // ks1
        load_frags<TRANSB>(aBuf, bBuf, 3, aLane, bLane, af[1], bf[1]);
        do_mmas(acc, af[0], bf[0]);                       // ks2

        cp_wait1();
        __syncthreads();

        if (t + 1 < NK) {
            const uint32_t aN = sbase + (uint32_t)((t + 1) % NSTAGE) * STAGE_B;
            load_frags<TRANSB>(aN, aN + A_TILE, 0, aLane, bLane, af[0], bf[0]);
        }
        do_mmas(acc, af[1], bf[1]);                       // ks3
    }

    // ---- epilogue ----
    float badd[8][2];
    #pragma unroll
    for (int nb = 0; nb < 8; nb++) {
        const int col = wn * 64 + nb * 8 + tq * 2;
        badd[nb][0] = bias ? __ldg(bias + bx * TN + col)     : 0.f;
        badd[nb][1] = bias ? __ldg(bias + bx * TN + col + 1) : 0.f;
    }
    if (halfOut) {
        __half* C = (__half*)Cv + (long long)bz * sC + (long long)(by * TM) * ldc + bx * TN;
        #pragma unroll
        for (int mb = 0; mb < 4; mb++) {
            const int row = wm * 64 + mb * 16 + g;
            #pragma unroll
            for (int nb = 0; nb < 8; nb++) {
                const int col = wn * 64 + nb * 8 + tq * 2;
                __half2 v0 = __floats2half2_rn(fmaf(acc[mb][nb][0], cmul, badd[nb][0]),
                                               fmaf(acc[mb][nb][1], cmul, badd[nb][1]));
                __half2 v1 = __floats2half2_rn(fmaf(acc[mb][nb][2], cmul, badd[nb][0]),
                                               fmaf(acc[mb][nb][3], cmul, badd[nb][1]));
                *(__half2*)(C + (long long)row * ldc + col)       = v0;
                *(__half2*)(C + (long long)(row + 8) * ldc + col) = v1;
            }
        }
    } else {
        float* C = (float*)Cv + (long long)bz * sC + (long long)(by * TM) * ldc + bx * TN;
        #pragma unroll
        for (int mb = 0; mb < 4; mb++) {
            const int row = wm * 64 + mb * 16 + g;
            #pragma unroll
            for (int nb = 0; nb < 8; nb++) {
                const int col = wn * 64 + nb * 8 + tq * 2;
                *(float2*)(C + (long long)row * ldc + col) =
                    make_float2(fmaf(acc[mb][nb][0], cmul, badd[nb][0]),
                                fmaf(acc[mb][nb][1], cmul, badd[nb][1]));
                *(float2*)(C + (long long)(row + 8) * ldc + col) =
                    make_float2(fmaf(acc[mb][nb][2], cmul, badd[nb][0]),
                                fmaf(acc[mb][nb][3], cmul, badd[nb][1]));
            }
        }
    }
}

// ---------------------------------------------------------------------------
// Elementwise f32 -> fp16 (for x). Grid-stride float4 -> 2x half2.
// ---------------------------------------------------------------------------
__global__ void f32_to_h_kernel(const float* __restrict__ in, __half* __restrict__ out,
                                size_t n4)
{
    size_t i = (size_t)blockIdx.x * blockDim.x + threadIdx.x;
    size_t stride = (size_t)gridDim.x * blockDim.x;
    for (; i < n4; i += stride) {
        float4 v = ((const float4*)in)[i];
        __half2* o = (__half2*)(out + i * 4);
        o[0] = __floats2half2_rn(v.x, v.y);
        o[1] = __floats2half2_rn(v.z, v.w);
    }
}

// ---------------------------------------------------------------------------
// Transpose f32 -> fp16: out[c][r] = h(in[r][c]).  (for W^T)
// ---------------------------------------------------------------------------
__global__ void transpose_f2h(const float* __restrict__ in, int ldin,
                              __half* __restrict__ out, int ldout)
{
    __shared__ float tile[32][33];
    const int c0 = blockIdx.x << 5;
    const int r0 = blockIdx.y << 5;
    const int x = threadIdx.x, y = threadIdx.y;     // 32 x 8
    #pragma unroll
    for (int j = 0; j < 32; j += 8)
        tile[y + j][x] = in[(long long)(r0 + y + j) * ldin + c0 + x];
    __syncthreads();
    #pragma unroll
    for (int j = 0; j < 32; j += 8)
        out[(long long)(c0 + y + j) * ldout + r0 + x] = __float2half_rn(tile[x][y + j]);
}

// ---------------------------------------------------------------------------
// Row softmax over 4096 pre-scaled f32 scores; writes fp16 probabilities.
// ---------------------------------------------------------------------------
__device__ __forceinline__ float warpMax(float v) {
    #pragma unroll
    for (int o = 16; o > 0; o >>= 1) v = fmaxf(v, __shfl_xor_sync(0xffffffffu, v, o));
    return v;
}
__device__ __forceinline__ float warpSum(float v) {
    #pragma unroll
    for (int o = 16; o > 0; o >>= 1) v += __shfl_xor_sync(0xffffffffu, v, o);
    return v;
}

__global__ __launch_bounds__(256, 4)
void softmax4096(const float* __restrict__ s, __half* __restrict__ pOut)
{
    const float* p = s + (long long)blockIdx.x * 4096;
    __half* po = pOut + (long long)blockIdx.x * 4096;
    const int t = threadIdx.x;
    const int lane = t & 31, wid = t >> 5;
    __shared__ float red[8];

    float4 v[4];
    #pragma unroll
    for (int i = 0; i < 4; i++) v[i] = *(const float4*)(p + i * 1024 + t * 4);

    float m = v[0].x;
    #pragma unroll
    for (int i = 0; i < 4; i++) {
        m = fmaxf(m, v[i].x); m = fmaxf(m, v[i].y);
        m = fmaxf(m, v[i].z); m = fmaxf(m, v[i].w);
    }
    m = warpMax(m);
    if (lane == 0) red[wid] = m;
    __syncthreads();
    m = red[0];
    #pragma unroll
    for (int j = 1; j < 8; j++) m = fmaxf(m, red[j]);

    float sum = 0.f;
    #pragma unroll
    for (int i = 0; i < 4; i++) {
        v[i].x = __expf(v[i].x - m); v[i].y = __expf(v[i].y - m);
        v[i].z = __expf(v[i].z - m); v[i].w = __expf(v[i].w - m);
        sum += v[i].x + v[i].y + v[i].z + v[i].w;
    }
    sum = warpSum(sum);
    __syncthreads();
    if (lane == 0) red[wid] = sum;
    __syncthreads();
    float tot = red[0];
    #pragma unroll
    for (int j = 1; j < 8; j++) tot += red[j];
    const float inv = 1.0f / tot;

    #pragma unroll
    for (int i = 0; i < 4; i++) {
        __half2* o = (__half2*)(po + i * 1024 + t * 4);
        o[0] = __floats2half2_rn(v[i].x * inv, v[i].y * inv);
        o[1] = __floats2half2_rn(v[i].z * inv, v[i].w * inv);
    }
}

// ---------------------------------------------------------------------------
// Launch
// ---------------------------------------------------------------------------
extern "C" void kernel_launch(void* const* d_in, const int* in_sizes, int n_in,
                              void* d_out, int out_size)
{
    (void)in_sizes; (void)n_in; (void)out_size;
    const float* x = (const float*)d_in[0];   // [B,S,D]
    const float* W = (const float*)d_in[1];   // [D,3D]
    const float* b = (const float*)d_in[2];   // [3D]
    float* out = (float*)d_out;               // [B,S,D]

    __half *xh, *wth, *qkvh, *ph;
    float *sc;
    cudaGetSymbolAddress((void**)&xh,   g_xh);
    cudaGetSymbolAddress((void**)&wth,  g_wth);
    cudaGetSymbolAddress((void**)&qkvh, g_qkvh);
    cudaGetSymbolAddress((void**)&sc,   g_sc);
    cudaGetSymbolAddress((void**)&ph,   g_ph);

    cudaFuncSetAttribute(gemm_f16mma<0>, cudaFuncAttributeMaxDynamicSharedMemorySize, SMEM_MAX);
    cudaFuncSetAttribute(gemm_f16mma<1>, cudaFuncAttributeMaxDynamicSharedMemorySize, SMEM_MAX);

    // 0a) xh = fp16(x)
    f32_to_h_kernel<<<1024, 256>>>(x, xh, (size_t)BDIM * SDIM * DDIM / 4);

    // 0b) Wth[e][d] = fp16(W[d][e])
    transpose_f2h<<<dim3(3 * DDIM / 32, DDIM / 32, 1), dim3(32, 8)>>>(
        W, 3 * DDIM, wth, DDIM);

    // 1) qkvh = fp16(xh @ Wth^T + b)   (M=16384, N=3072, K=1024)
    gemm_f16mma<0><<<dim3(3 * DDIM / TN, BDIM * SDIM / TM, 1), 256, SMEM_MAX>>>(
        xh,   DDIM, 0LL,
        wth,  DDIM, 0LL,
        qkvh, 3 * DDIM, 0LL,
        DDIM, b, 1.0f, 1);

    // 2) scores = (Q @ K^T) * 1/32   (per batch: M=4096, N=4096, K=1024), f32
    gemm_f16mma<0><<<dim3(SDIM / TN, SDIM / TM, BDIM), 256, SMEM_MAX>>>(
        qkvh,        3 * DDIM, (long long)SDIM * 3 * DDIM,
        qkvh + DDIM, 3 * DDIM, (long long)SDIM * 3 * DDIM,
        sc,          SDIM,     (long long)SDIM * SDIM,
        DDIM, (const float*)0, 0.03125f, 0);

    // 3) softmax rows: f32 scaled scores -> fp16 probs
    softmax4096<<<BDIM * SDIM, 256>>>(sc, ph);

    // 4) out = P @ V   (per batch: M=4096, N=1024, K=4096), V read in natural
    //    [s][d] layout directly from qkvh via ldmatrix.trans, f32 out
    gemm_f16mma<1><<<dim3(DDIM / TN, SDIM / TM, BDIM), 256, SMEM_MAX>>>(
        ph,              SDIM,     (long long)SDIM * SDIM,
        qkvh + 2 * DDIM, 3 * DDIM, (long long)SDIM * 3 * DDIM,
        out,             DDIM,     (long long)SDIM * DDIM,
        SDIM, (const float*)0, 1.0f, 0);
}